// round 1
// baseline (speedup 1.0000x reference)
#include <cuda_runtime.h>
#include <math.h>

#define BB 4
#define NN 4096
#define DD 1024
#define HH 16
#define HDIM 64
#define GG 512
#define BNTOK (BB*NN)

// ---------------- scratch (device globals; no allocations allowed) ----------
__device__ float g_wv[(size_t)BNTOK * DD];            // 64MB  wv = v * ||k||
__device__ float g_field[(size_t)BB * HH * GG * HDIM]; // 8MB
__device__ float g_conv[(size_t)BB * HH * GG * HDIM];  // 8MB
__device__ float g_A[(size_t)BB * GG * DD];            // 8MB  repacked conv
__device__ float g_R[(size_t)BB * GG * DD];            // 8MB  per-bin output rows

// Replicates jnp: pos = (n/4095.0f)*511.0f ; int32 trunc ; clip
__device__ __forceinline__ int bin_of(int n) {
    float p = ((float)n / 4095.0f) * 511.0f;
    int g = (int)p;
    g = g < 0 ? 0 : g;
    return g > 511 ? 511 : g;
}

// ---------------------------------------------------------------------------
// Kernel 1: fused K/V GEMM (per head) + ||k|| + wv write.
// Block: 128 tokens x 1 head (64 cols), both k and v. 256 threads, 8x4 micro.
// ---------------------------------------------------------------------------
__global__ __launch_bounds__(256) void kv_field_kernel(
    const float* __restrict__ x,
    const float* __restrict__ kw, const float* __restrict__ kb,
    const float* __restrict__ vw, const float* __restrict__ vb)
{
    __shared__ float sx[16][132];   // [kk][token]
    __shared__ float sk[16][68];    // [kk][col]
    __shared__ float sv[16][68];
    __shared__ float red[128][17];
    __shared__ float smag[128];

    const int tok0 = blockIdx.x * 128;
    const int h    = blockIdx.y;
    const int t    = threadIdx.x;
    const int tx   = t & 15;        // col group: cols tx*4..tx*4+3
    const int ty   = t >> 4;        // token group: tokens ty*8..ty*8+7

    float ck[8][4] = {}, cv[8][4] = {};

    const float* xg  = x  + (size_t)tok0 * DD;
    const float* kwg = kw + (size_t)h * HDIM * DD;
    const float* vwg = vw + (size_t)h * HDIM * DD;

    for (int k0 = 0; k0 < DD; k0 += 16) {
        // x tile: 128 tokens x 16 k, transposed into sx[kk][token]
        #pragma unroll
        for (int it = 0; it < 2; ++it) {
            int idx = t + it * 256;        // 0..511
            int r   = idx >> 2;            // token 0..127
            int c4  = (idx & 3) * 4;       // k sub-offset
            float4 vx = *reinterpret_cast<const float4*>(xg + (size_t)r * DD + k0 + c4);
            sx[c4 + 0][r] = vx.x; sx[c4 + 1][r] = vx.y;
            sx[c4 + 2][r] = vx.z; sx[c4 + 3][r] = vx.w;
        }
        // weight tiles: 64 rows (head cols) x 16 k each
        {
            int r  = t >> 2;               // 0..63
            int c4 = (t & 3) * 4;
            float4 a = *reinterpret_cast<const float4*>(kwg + (size_t)r * DD + k0 + c4);
            sk[c4 + 0][r] = a.x; sk[c4 + 1][r] = a.y; sk[c4 + 2][r] = a.z; sk[c4 + 3][r] = a.w;
            float4 b = *reinterpret_cast<const float4*>(vwg + (size_t)r * DD + k0 + c4);
            sv[c4 + 0][r] = b.x; sv[c4 + 1][r] = b.y; sv[c4 + 2][r] = b.z; sv[c4 + 3][r] = b.w;
        }
        __syncthreads();
        #pragma unroll
        for (int kk = 0; kk < 16; ++kk) {
            float af[8], bkf[4], bvf[4];
            #pragma unroll
            for (int i = 0; i < 8; ++i) af[i] = sx[kk][ty * 8 + i];
            #pragma unroll
            for (int j = 0; j < 4; ++j) { bkf[j] = sk[kk][tx * 4 + j]; bvf[j] = sv[kk][tx * 4 + j]; }
            #pragma unroll
            for (int i = 0; i < 8; ++i)
                #pragma unroll
                for (int j = 0; j < 4; ++j) {
                    ck[i][j] = fmaf(af[i], bkf[j], ck[i][j]);
                    cv[i][j] = fmaf(af[i], bvf[j], cv[i][j]);
                }
        }
        __syncthreads();
    }

    float kbv[4], vbv[4];
    #pragma unroll
    for (int j = 0; j < 4; ++j) {
        kbv[j] = kb[h * HDIM + tx * 4 + j];
        vbv[j] = vb[h * HDIM + tx * 4 + j];
    }

    // per-token sum of squares of k (partial over this thread's 4 cols)
    #pragma unroll
    for (int i = 0; i < 8; ++i) {
        float s = 0.f;
        #pragma unroll
        for (int j = 0; j < 4; ++j) {
            float kv = ck[i][j] + kbv[j];
            s = fmaf(kv, kv, s);
        }
        red[ty * 8 + i][tx] = s;
    }
    __syncthreads();
    if (t < 128) {
        float s = 0.f;
        #pragma unroll
        for (int j = 0; j < 16; ++j) s += red[t][j];
        smag[t] = sqrtf(s);
    }
    __syncthreads();

    // wv = (v + vb) * ||k||  ->  g_wv[token][h*64 + col]
    #pragma unroll
    for (int i = 0; i < 8; ++i) {
        int tl = ty * 8 + i;
        float m = smag[tl];
        float4 o;
        o.x = (cv[i][0] + vbv[0]) * m;
        o.y = (cv[i][1] + vbv[1]) * m;
        o.z = (cv[i][2] + vbv[2]) * m;
        o.w = (cv[i][3] + vbv[3]) * m;
        *reinterpret_cast<float4*>(g_wv + (size_t)(tok0 + tl) * DD + h * HDIM + tx * 4) = o;
    }
}

// ---------------------------------------------------------------------------
// Kernel 2: segment-sum into field. Each block = one (bin g, b*H+h), 64 threads.
// Bins are contiguous token ranges of 8-9 tokens; deterministic, no atomics.
// ---------------------------------------------------------------------------
__global__ void field_kernel()
{
    int g  = blockIdx.x;
    int bh = blockIdx.y;
    int b  = bh >> 4, h = bh & 15;
    int d  = threadIdx.x;
    int n0 = (int)(((long long)g * 4095) / 511) - 2;
    if (n0 < 0) n0 = 0;
    float s = 0.f;
    for (int n = n0; n < n0 + 14 && n < NN; ++n) {
        if (bin_of(n) == g)
            s += g_wv[((size_t)(b * NN + n)) * DD + h * HDIM + d];
    }
    g_field[((size_t)bh * GG + g) * HDIM + d] = s;
}

// ---------------------------------------------------------------------------
// Kernel 3: circular exp-kernel convolution via anchor + geometric recursion.
// conv[g] = sum_{d=1..256} (a^d/Z) field[(g-256+d) mod 512],  a = exp(-1/3)
//         = a*conv[g+1] + (a/Z)*field[(g+257) mod 512]  (+ O(a^257) ~ 5e-38)
// One block per (b,h): field slice cached in 128KB smem.
// ---------------------------------------------------------------------------
#define TAPS 144
__global__ void conv_kernel()
{
    extern __shared__ float sf[];        // GG*HDIM floats
    __shared__ float wsh[TAPS];
    int bh = blockIdx.x;
    const float* F = g_field + (size_t)bh * GG * HDIM;
    for (int i = threadIdx.x; i < GG * HDIM; i += blockDim.x)
        sf[i] = F[i];
    if (threadIdx.x < TAPS) {
        float Z = 0.f;
        for (int dd = 256; dd >= 1; --dd) Z += expf(-(float)dd / 3.0f);
        Z += 1e-8f;
        wsh[threadIdx.x] = expf(-(float)(threadIdx.x + 1) / 3.0f) / Z;
    }
    __syncthreads();

    int d    = threadIdx.x & 63;
    int g0   = (threadIdx.x >> 6) * 64;  // 8 strips of 64 g-positions
    int gtop = g0 + 63;

    // direct anchor at strip top (small weights first for accuracy)
    float acc = 0.f;
    for (int j = TAPS - 1; j >= 0; --j)
        acc = fmaf(wsh[j], sf[((gtop + 257 + j) & 511) * HDIM + d], acc);

    float* out = g_conv + (size_t)bh * GG * HDIM;
    out[gtop * HDIM + d] = acc;

    const float a  = 0.7165313105737893f;  // exp(-1/3)
    const float w0 = wsh[0];
    float C = acc;
    for (int g = gtop - 1; g >= g0; --g) {
        C = fmaf(a, C, w0 * sf[((g + 257) & 511) * HDIM + d]);
        out[g * HDIM + d] = C;
    }
}

// ---------------------------------------------------------------------------
// Kernel 4: repack conv (B,H,G,hd) -> A (B*G, D) rows for the output GEMM.
// ---------------------------------------------------------------------------
__global__ void repack_kernel()
{
    int m = blockIdx.x;              // b*G + g
    int b = m >> 9, g = m & 511;
    for (int k = threadIdx.x; k < DD; k += blockDim.x) {
        int h = k >> 6, d = k & 63;
        g_A[(size_t)m * DD + k] = g_conv[(((size_t)(b * HH + h)) * GG + g) * HDIM + d];
    }
}

// ---------------------------------------------------------------------------
// Kernel 5: R = A @ out_w.T + out_b   (only B*G = 2048 distinct rows!)
// ---------------------------------------------------------------------------
__global__ __launch_bounds__(256) void out_gemm_kernel(
    const float* __restrict__ ow, const float* __restrict__ ob)
{
    __shared__ float sA[16][132];
    __shared__ float sW[16][68];
    const int m0 = blockIdx.x * 128;
    const int j0 = blockIdx.y * 64;
    const int t  = threadIdx.x;
    const int tx = t & 15;
    const int ty = t >> 4;
    float c[8][4] = {};
    const float* Ag = g_A + (size_t)m0 * DD;
    const float* Wg = ow  + (size_t)j0 * DD;

    for (int k0 = 0; k0 < DD; k0 += 16) {
        #pragma unroll
        for (int it = 0; it < 2; ++it) {
            int idx = t + it * 256;
            int r   = idx >> 2;
            int c4  = (idx & 3) * 4;
            float4 va = *reinterpret_cast<const float4*>(Ag + (size_t)r * DD + k0 + c4);
            sA[c4 + 0][r] = va.x; sA[c4 + 1][r] = va.y;
            sA[c4 + 2][r] = va.z; sA[c4 + 3][r] = va.w;
        }
        {
            int r  = t >> 2;
            int c4 = (t & 3) * 4;
            float4 vw4 = *reinterpret_cast<const float4*>(Wg + (size_t)r * DD + k0 + c4);
            sW[c4 + 0][r] = vw4.x; sW[c4 + 1][r] = vw4.y;
            sW[c4 + 2][r] = vw4.z; sW[c4 + 3][r] = vw4.w;
        }
        __syncthreads();
        #pragma unroll
        for (int kk = 0; kk < 16; ++kk) {
            float af[8], bf4[4];
            #pragma unroll
            for (int i = 0; i < 8; ++i) af[i] = sA[kk][ty * 8 + i];
            #pragma unroll
            for (int j = 0; j < 4; ++j) bf4[j] = sW[kk][tx * 4 + j];
            #pragma unroll
            for (int i = 0; i < 8; ++i)
                #pragma unroll
                for (int j = 0; j < 4; ++j)
                    c[i][j] = fmaf(af[i], bf4[j], c[i][j]);
        }
        __syncthreads();
    }
    float bias[4];
    #pragma unroll
    for (int j = 0; j < 4; ++j) bias[j] = ob[j0 + tx * 4 + j];
    #pragma unroll
    for (int i = 0; i < 8; ++i) {
        float4 o;
        o.x = c[i][0] + bias[0]; o.y = c[i][1] + bias[1];
        o.z = c[i][2] + bias[2]; o.w = c[i][3] + bias[3];
        *reinterpret_cast<float4*>(g_R + (size_t)(m0 + ty * 8 + i) * DD + j0 + tx * 4) = o;
    }
}

// ---------------------------------------------------------------------------
// Kernel 6: scatter per-bin rows back to all tokens (float4).
// ---------------------------------------------------------------------------
__global__ void scatter_kernel(float* __restrict__ out)
{
    int idx = blockIdx.x * blockDim.x + threadIdx.x;   // over BNTOK*256 float4s
    int c4  = idx & 255;
    int tok = idx >> 8;
    int n   = tok & (NN - 1);
    int b   = tok >> 12;
    int g   = bin_of(n);
    reinterpret_cast<float4*>(out)[(size_t)tok * 256 + c4] =
        reinterpret_cast<const float4*>(g_R)[((size_t)(b * GG + g)) * 256 + c4];
}

// ---------------------------------------------------------------------------
extern "C" void kernel_launch(void* const* d_in, const int* in_sizes, int n_in,
                              void* d_out, int out_size)
{
    const float* x  = (const float*)d_in[0];
    // d_in[1], d_in[2] are q_w, q_b — provably unused by the reference output.
    const float* kw = (const float*)d_in[3];
    const float* kb = (const float*)d_in[4];
    const float* vw = (const float*)d_in[5];
    const float* vb = (const float*)d_in[6];
    const float* ow = (const float*)d_in[7];
    const float* ob = (const float*)d_in[8];
    float* out = (float*)d_out;

    kv_field_kernel<<<dim3(BNTOK / 128, HH), 256>>>(x, kw, kb, vw, vb);
    field_kernel<<<dim3(GG, BB * HH), 64>>>();

    cudaFuncSetAttribute(conv_kernel, cudaFuncAttributeMaxDynamicSharedMemorySize,
                         GG * HDIM * (int)sizeof(float));
    conv_kernel<<<BB * HH, 512, GG * HDIM * sizeof(float)>>>();

    repack_kernel<<<BB * GG, 256>>>();
    out_gemm_kernel<<<dim3((BB * GG) / 128, DD / 64), 256>>>(ow, ob);
    scatter_kernel<<<(BNTOK * 256) / 256, 256>>>(out);
}

// round 2
// speedup vs baseline: 1.0813x; 1.0813x over previous
#include <cuda_runtime.h>
#include <math.h>

#define BB 4
#define NN 4096
#define DD 1024
#define HH 16
#define HDIM 64
#define GG 512
#define BNTOK (BB*NN)

typedef unsigned long long ull;

// ---------------- scratch (device globals; no allocations allowed) ----------
__device__ float g_wv[(size_t)BNTOK * DD];             // 64MB  wv = v * ||k||
__device__ float g_field[(size_t)BB * HH * GG * HDIM]; // 8MB
__device__ float g_conv[(size_t)BB * HH * GG * HDIM];  // 8MB
__device__ float g_A[(size_t)BB * GG * DD];            // 8MB  repacked conv
__device__ float g_R[(size_t)BB * GG * DD];            // 8MB  per-bin output rows

// Replicates jnp: pos = (n/4095.0f)*511.0f ; int32 trunc ; clip
__device__ __forceinline__ int bin_of(int n) {
    float p = ((float)n / 4095.0f) * 511.0f;
    int g = (int)p;
    g = g < 0 ? 0 : g;
    return g > 511 ? 511 : g;
}

// ---------------- packed f32x2 helpers (Blackwell FFMA2) ---------------------
__device__ __forceinline__ ull pack2(float x, float y) {
    ull r;
    asm("mov.b64 %0, {%1, %2};" : "=l"(r) : "f"(x), "f"(y));
    return r;
}
__device__ __forceinline__ void fma2(ull &c, ull a, ull b) {
    asm("fma.rn.f32x2 %0, %1, %2, %0;" : "+l"(c) : "l"(a), "l"(b));
}
__device__ __forceinline__ float2 unpack2(ull v) {
    float2 f;
    asm("mov.b64 {%0, %1}, %2;" : "=f"(f.x), "=f"(f.y) : "l"(v));
    return f;
}

// ---------------------------------------------------------------------------
// Kernel 1: fused K/V GEMM (per head) + ||k|| + wv write.
// Block: 128 tokens x 1 head (64 cols), k and v together. 256 threads.
// Micro-tile 8x4 per thread, accumulators packed 2-wide along tokens (FFMA2).
// ---------------------------------------------------------------------------
__global__ __launch_bounds__(256) void kv_field_kernel(
    const float* __restrict__ x,
    const float* __restrict__ kw, const float* __restrict__ kb,
    const float* __restrict__ vw, const float* __restrict__ vb)
{
    __shared__ float sx[16][132];   // [kk][token]
    __shared__ float sk[16][68];    // [kk][col]
    __shared__ float sv[16][68];
    __shared__ float red[128][17];
    __shared__ float smag[128];

    const int tok0 = blockIdx.x * 128;
    const int h    = blockIdx.y;
    const int t    = threadIdx.x;
    const int tx   = t & 15;        // col group: cols tx*4..tx*4+3
    const int ty   = t >> 4;        // token group: tokens ty*8..ty*8+7

    // packed accumulators: [token-pair][col], pair = tokens (2ip, 2ip+1)
    ull ck2[4][4], cv2[4][4];
    #pragma unroll
    for (int i = 0; i < 4; ++i)
        #pragma unroll
        for (int j = 0; j < 4; ++j) { ck2[i][j] = 0ULL; cv2[i][j] = 0ULL; }

    const float* xg  = x  + (size_t)tok0 * DD;
    const float* kwg = kw + (size_t)h * HDIM * DD;
    const float* vwg = vw + (size_t)h * HDIM * DD;

    for (int k0 = 0; k0 < DD; k0 += 16) {
        // x tile: 128 tokens x 16 k, transposed into sx[kk][token]
        #pragma unroll
        for (int it = 0; it < 2; ++it) {
            int idx = t + it * 256;        // 0..511
            int r   = idx >> 2;            // token 0..127
            int c4  = (idx & 3) * 4;       // k sub-offset
            float4 vx = *reinterpret_cast<const float4*>(xg + (size_t)r * DD + k0 + c4);
            sx[c4 + 0][r] = vx.x; sx[c4 + 1][r] = vx.y;
            sx[c4 + 2][r] = vx.z; sx[c4 + 3][r] = vx.w;
        }
        // weight tiles: 64 rows (head cols) x 16 k each
        {
            int r  = t >> 2;               // 0..63
            int c4 = (t & 3) * 4;
            float4 a = *reinterpret_cast<const float4*>(kwg + (size_t)r * DD + k0 + c4);
            sk[c4 + 0][r] = a.x; sk[c4 + 1][r] = a.y; sk[c4 + 2][r] = a.z; sk[c4 + 3][r] = a.w;
            float4 b = *reinterpret_cast<const float4*>(vwg + (size_t)r * DD + k0 + c4);
            sv[c4 + 0][r] = b.x; sv[c4 + 1][r] = b.y; sv[c4 + 2][r] = b.z; sv[c4 + 3][r] = b.w;
        }
        __syncthreads();
        #pragma unroll
        for (int kk = 0; kk < 16; ++kk) {
            // a pairs: 8 contiguous tokens -> 4 x 64-bit LDS (broadcast across tx lanes)
            const ull* ap = reinterpret_cast<const ull*>(&sx[kk][ty * 8]);
            ull a2[4];
            #pragma unroll
            for (int ip = 0; ip < 4; ++ip) a2[ip] = ap[ip];
            // b: 4 contiguous cols each -> float4 LDS, then duplicate-pack
            float4 bk4 = *reinterpret_cast<const float4*>(&sk[kk][tx * 4]);
            float4 bv4 = *reinterpret_cast<const float4*>(&sv[kk][tx * 4]);
            ull bk2[4] = { pack2(bk4.x, bk4.x), pack2(bk4.y, bk4.y),
                           pack2(bk4.z, bk4.z), pack2(bk4.w, bk4.w) };
            ull bv2[4] = { pack2(bv4.x, bv4.x), pack2(bv4.y, bv4.y),
                           pack2(bv4.z, bv4.z), pack2(bv4.w, bv4.w) };
            #pragma unroll
            for (int ip = 0; ip < 4; ++ip) {
                #pragma unroll
                for (int j = 0; j < 4; ++j) {
                    fma2(ck2[ip][j], a2[ip], bk2[j]);
                    fma2(cv2[ip][j], a2[ip], bv2[j]);
                }
            }
        }
        __syncthreads();
    }

    // unpack to scalar tiles
    float ckf[8][4], cvf[8][4];
    #pragma unroll
    for (int ip = 0; ip < 4; ++ip)
        #pragma unroll
        for (int j = 0; j < 4; ++j) {
            float2 a = unpack2(ck2[ip][j]);
            ckf[2 * ip][j] = a.x; ckf[2 * ip + 1][j] = a.y;
            float2 b = unpack2(cv2[ip][j]);
            cvf[2 * ip][j] = b.x; cvf[2 * ip + 1][j] = b.y;
        }

    float kbv[4], vbv[4];
    #pragma unroll
    for (int j = 0; j < 4; ++j) {
        kbv[j] = kb[h * HDIM + tx * 4 + j];
        vbv[j] = vb[h * HDIM + tx * 4 + j];
    }

    // per-token sum of squares of k (partial over this thread's 4 cols)
    #pragma unroll
    for (int i = 0; i < 8; ++i) {
        float s = 0.f;
        #pragma unroll
        for (int j = 0; j < 4; ++j) {
            float kv = ckf[i][j] + kbv[j];
            s = fmaf(kv, kv, s);
        }
        red[ty * 8 + i][tx] = s;
    }
    __syncthreads();
    if (t < 128) {
        float s = 0.f;
        #pragma unroll
        for (int j = 0; j < 16; ++j) s += red[t][j];
        smag[t] = sqrtf(s);
    }
    __syncthreads();

    // wv = (v + vb) * ||k||  ->  g_wv[token][h*64 + col]
    #pragma unroll
    for (int i = 0; i < 8; ++i) {
        int tl = ty * 8 + i;
        float m = smag[tl];
        float4 o;
        o.x = (cvf[i][0] + vbv[0]) * m;
        o.y = (cvf[i][1] + vbv[1]) * m;
        o.z = (cvf[i][2] + vbv[2]) * m;
        o.w = (cvf[i][3] + vbv[3]) * m;
        *reinterpret_cast<float4*>(g_wv + (size_t)(tok0 + tl) * DD + h * HDIM + tx * 4) = o;
    }
}

// ---------------------------------------------------------------------------
// Kernel 2: segment-sum into field. Each block = one (bin g, b*H+h), 64 threads.
// ---------------------------------------------------------------------------
__global__ void field_kernel()
{
    int g  = blockIdx.x;
    int bh = blockIdx.y;
    int b  = bh >> 4, h = bh & 15;
    int d  = threadIdx.x;
    int n0 = (int)(((long long)g * 4095) / 511) - 2;
    if (n0 < 0) n0 = 0;
    float s = 0.f;
    for (int n = n0; n < n0 + 14 && n < NN; ++n) {
        if (bin_of(n) == g)
            s += g_wv[((size_t)(b * NN + n)) * DD + h * HDIM + d];
    }
    g_field[((size_t)bh * GG + g) * HDIM + d] = s;
}

// ---------------------------------------------------------------------------
// Kernel 3: circular exp-kernel convolution via anchor + geometric recursion.
// ---------------------------------------------------------------------------
#define TAPS 144
__global__ void conv_kernel()
{
    extern __shared__ float sf[];        // GG*HDIM floats
    __shared__ float wsh[TAPS];
    int bh = blockIdx.x;
    const float* F = g_field + (size_t)bh * GG * HDIM;
    for (int i = threadIdx.x; i < GG * HDIM; i += blockDim.x)
        sf[i] = F[i];
    if (threadIdx.x < TAPS) {
        float Z = 0.f;
        for (int dd = 256; dd >= 1; --dd) Z += expf(-(float)dd / 3.0f);
        Z += 1e-8f;
        wsh[threadIdx.x] = expf(-(float)(threadIdx.x + 1) / 3.0f) / Z;
    }
    __syncthreads();

    int d    = threadIdx.x & 63;
    int g0   = (threadIdx.x >> 6) * 64;  // 8 strips of 64 g-positions
    int gtop = g0 + 63;

    float acc = 0.f;
    for (int j = TAPS - 1; j >= 0; --j)
        acc = fmaf(wsh[j], sf[((gtop + 257 + j) & 511) * HDIM + d], acc);

    float* out = g_conv + (size_t)bh * GG * HDIM;
    out[gtop * HDIM + d] = acc;

    const float a  = 0.7165313105737893f;  // exp(-1/3)
    const float w0 = wsh[0];
    float C = acc;
    for (int g = gtop - 1; g >= g0; --g) {
        C = fmaf(a, C, w0 * sf[((g + 257) & 511) * HDIM + d]);
        out[g * HDIM + d] = C;
    }
}

// ---------------------------------------------------------------------------
// Kernel 4: repack conv (B,H,G,hd) -> A (B*G, D)
// ---------------------------------------------------------------------------
__global__ void repack_kernel()
{
    int m = blockIdx.x;              // b*G + g
    int b = m >> 9, g = m & 511;
    for (int k = threadIdx.x; k < DD; k += blockDim.x) {
        int h = k >> 6, d = k & 63;
        g_A[(size_t)m * DD + k] = g_conv[(((size_t)(b * HH + h)) * GG + g) * HDIM + d];
    }
}

// ---------------------------------------------------------------------------
// Kernel 5: R = A @ out_w.T + out_b   (B*G = 2048 rows), FFMA2 mainloop
// ---------------------------------------------------------------------------
__global__ __launch_bounds__(256) void out_gemm_kernel(
    const float* __restrict__ ow, const float* __restrict__ ob)
{
    __shared__ float sA[16][132];
    __shared__ float sW[16][68];
    const int m0 = blockIdx.x * 128;
    const int j0 = blockIdx.y * 64;
    const int t  = threadIdx.x;
    const int tx = t & 15;
    const int ty = t >> 4;

    ull c2[4][4];
    #pragma unroll
    for (int i = 0; i < 4; ++i)
        #pragma unroll
        for (int j = 0; j < 4; ++j) c2[i][j] = 0ULL;

    const float* Ag = g_A + (size_t)m0 * DD;
    const float* Wg = ow  + (size_t)j0 * DD;

    for (int k0 = 0; k0 < DD; k0 += 16) {
        #pragma unroll
        for (int it = 0; it < 2; ++it) {
            int idx = t + it * 256;
            int r   = idx >> 2;
            int c4  = (idx & 3) * 4;
            float4 va = *reinterpret_cast<const float4*>(Ag + (size_t)r * DD + k0 + c4);
            sA[c4 + 0][r] = va.x; sA[c4 + 1][r] = va.y;
            sA[c4 + 2][r] = va.z; sA[c4 + 3][r] = va.w;
        }
        {
            int r  = t >> 2;
            int c4 = (t & 3) * 4;
            float4 vw4 = *reinterpret_cast<const float4*>(Wg + (size_t)r * DD + k0 + c4);
            sW[c4 + 0][r] = vw4.x; sW[c4 + 1][r] = vw4.y;
            sW[c4 + 2][r] = vw4.z; sW[c4 + 3][r] = vw4.w;
        }
        __syncthreads();
        #pragma unroll
        for (int kk = 0; kk < 16; ++kk) {
            const ull* ap = reinterpret_cast<const ull*>(&sA[kk][ty * 8]);
            ull a2[4];
            #pragma unroll
            for (int ip = 0; ip < 4; ++ip) a2[ip] = ap[ip];
            float4 b4 = *reinterpret_cast<const float4*>(&sW[kk][tx * 4]);
            ull b2[4] = { pack2(b4.x, b4.x), pack2(b4.y, b4.y),
                          pack2(b4.z, b4.z), pack2(b4.w, b4.w) };
            #pragma unroll
            for (int ip = 0; ip < 4; ++ip)
                #pragma unroll
                for (int j = 0; j < 4; ++j)
                    fma2(c2[ip][j], a2[ip], b2[j]);
        }
        __syncthreads();
    }

    float bias[4];
    #pragma unroll
    for (int j = 0; j < 4; ++j) bias[j] = ob[j0 + tx * 4 + j];
    #pragma unroll
    for (int ip = 0; ip < 4; ++ip) {
        float2 r0[4];
        #pragma unroll
        for (int j = 0; j < 4; ++j) r0[j] = unpack2(c2[ip][j]);
        float4 o0, o1;
        o0.x = r0[0].x + bias[0]; o0.y = r0[1].x + bias[1];
        o0.z = r0[2].x + bias[2]; o0.w = r0[3].x + bias[3];
        o1.x = r0[0].y + bias[0]; o1.y = r0[1].y + bias[1];
        o1.z = r0[2].y + bias[2]; o1.w = r0[3].y + bias[3];
        *reinterpret_cast<float4*>(g_R + (size_t)(m0 + ty * 8 + 2 * ip) * DD + j0 + tx * 4) = o0;
        *reinterpret_cast<float4*>(g_R + (size_t)(m0 + ty * 8 + 2 * ip + 1) * DD + j0 + tx * 4) = o1;
    }
}

// ---------------------------------------------------------------------------
// Kernel 6: scatter per-bin rows back to all tokens (float4).
// ---------------------------------------------------------------------------
__global__ void scatter_kernel(float* __restrict__ out)
{
    int idx = blockIdx.x * blockDim.x + threadIdx.x;   // over BNTOK*256 float4s
    int c4  = idx & 255;
    int tok = idx >> 8;
    int n   = tok & (NN - 1);
    int b   = tok >> 12;
    int g   = bin_of(n);
    reinterpret_cast<float4*>(out)[(size_t)tok * 256 + c4] =
        reinterpret_cast<const float4*>(g_R)[((size_t)(b * GG + g)) * 256 + c4];
}

// ---------------------------------------------------------------------------
extern "C" void kernel_launch(void* const* d_in, const int* in_sizes, int n_in,
                              void* d_out, int out_size)
{
    const float* x  = (const float*)d_in[0];
    // d_in[1], d_in[2] are q_w, q_b — unused by the reference output.
    const float* kw = (const float*)d_in[3];
    const float* kb = (const float*)d_in[4];
    const float* vw = (const float*)d_in[5];
    const float* vb = (const float*)d_in[6];
    const float* ow = (const float*)d_in[7];
    const float* ob = (const float*)d_in[8];
    float* out = (float*)d_out;

    kv_field_kernel<<<dim3(BNTOK / 128, HH), 256>>>(x, kw, kb, vw, vb);
    field_kernel<<<dim3(GG, BB * HH), 64>>>();

    cudaFuncSetAttribute(conv_kernel, cudaFuncAttributeMaxDynamicSharedMemorySize,
                         GG * HDIM * (int)sizeof(float));
    conv_kernel<<<BB * HH, 512, GG * HDIM * sizeof(float)>>>();

    repack_kernel<<<BB * GG, 256>>>();
    out_gemm_kernel<<<dim3((BB * GG) / 128, DD / 64), 256>>>(ow, ob);
    scatter_kernel<<<(BNTOK * 256) / 256, 256>>>(out);
}

// round 4
// speedup vs baseline: 1.9702x; 1.8221x over previous
#include <cuda_runtime.h>
#include <cuda_bf16.h>
#include <math.h>
#include <stdint.h>

#define BB 4
#define NN 4096
#define DD 1024
#define HH 16
#define HDIM 64
#define GG 512
#define BNTOK (BB*NN)

// ---------------- scratch (device globals; no allocations allowed) ----------
__device__ float g_wv[(size_t)BNTOK * DD];              // 64MB  wv = v * ||k||
__device__ float g_field[(size_t)BB * HH * GG * HDIM];  // 8MB
__device__ float g_conv[(size_t)BB * HH * GG * HDIM];   // 8MB
__device__ float g_R[(size_t)BB * GG * DD];             // 8MB  per-bin out rows

__device__ __nv_bfloat16 g_xhi[(size_t)BNTOK * DD];     // 32MB
__device__ __nv_bfloat16 g_xlo[(size_t)BNTOK * DD];     // 32MB
__device__ __nv_bfloat16 g_wkvhi[(size_t)2048 * DD];    // packed [k|v] per head
__device__ __nv_bfloat16 g_wkvlo[(size_t)2048 * DD];
__device__ __nv_bfloat16 g_owhi[(size_t)DD * DD];
__device__ __nv_bfloat16 g_owlo[(size_t)DD * DD];
__device__ __nv_bfloat16 g_Ahi[(size_t)BB * GG * DD];   // conv repacked, bf16 split
__device__ __nv_bfloat16 g_Alo[(size_t)BB * GG * DD];

// Replicates jnp: pos = (n/4095.0f)*511.0f ; int32 trunc ; clip
__device__ __forceinline__ int bin_of(int n) {
    float p = ((float)n / 4095.0f) * 511.0f;
    int g = (int)p;
    g = g < 0 ? 0 : g;
    return g > 511 ? 511 : g;
}

// ---------------- baseline-PTX tensor helpers (sm_80+, ok on compute_103) ---
__device__ __forceinline__ uint32_t smem_u32(const void* p) {
    uint32_t a;
    asm("{ .reg .u64 t; cvta.to.shared.u64 t, %1; cvt.u32.u64 %0, t; }" : "=r"(a) : "l"(p));
    return a;
}
__device__ __forceinline__ void ldmx4(uint32_t* r, uint32_t a) {
    asm volatile("ldmatrix.sync.aligned.m8n8.x4.shared.b16 {%0,%1,%2,%3}, [%4];"
        : "=r"(r[0]), "=r"(r[1]), "=r"(r[2]), "=r"(r[3]) : "r"(a));
}
__device__ __forceinline__ void mma16816(float* c, const uint32_t* a, const uint32_t* b) {
    asm volatile("mma.sync.aligned.m16n8k16.row.col.f32.bf16.bf16.f32 "
        "{%0,%1,%2,%3}, {%4,%5,%6,%7}, {%8,%9}, {%0,%1,%2,%3};"
        : "+f"(c[0]), "+f"(c[1]), "+f"(c[2]), "+f"(c[3])
        : "r"(a[0]), "r"(a[1]), "r"(a[2]), "r"(a[3]), "r"(b[0]), "r"(b[1]));
}
#define CP_ASYNC(d, s) asm volatile("cp.async.cg.shared.global [%0], [%1], 16;" :: "r"(d), "l"(s) : "memory")
#define CP_COMMIT()    asm volatile("cp.async.commit_group;" ::: "memory")
#define CP_WAIT2()     asm volatile("cp.async.wait_group 2;" ::: "memory")
#define CP_WAIT1()     asm volatile("cp.async.wait_group 1;" ::: "memory")
#define CP_WAIT0()     asm volatile("cp.async.wait_group 0;" ::: "memory")

// GEMM tiling: block 128x128, 8 warps (2x4), warp tile 64x32, K chunk 32
#define KC       32
#define NCH      32                 // 1024 / 32
#define ROWPITCH 80                 // 64B row + 16B pad (conflict-free ldmatrix)
#define A_HI_OFF 0
#define A_LO_OFF 10240
#define B_HI_OFF 20480
#define B_LO_OFF 30720
#define STAGE    40960
#define DSMEM    (3*STAGE)          // 122880

// ---------------------------------------------------------------------------
// fp32 -> bf16 hi/lo split conversions
// ---------------------------------------------------------------------------
__global__ void conv_x_kernel(const float* __restrict__ x)
{
    size_t i = (size_t)blockIdx.x * blockDim.x + threadIdx.x;
    float4 v = reinterpret_cast<const float4*>(x)[i];
    __nv_bfloat16 h0 = __float2bfloat16(v.x), h1 = __float2bfloat16(v.y);
    __nv_bfloat16 h2 = __float2bfloat16(v.z), h3 = __float2bfloat16(v.w);
    __nv_bfloat162* HI = reinterpret_cast<__nv_bfloat162*>(g_xhi);
    __nv_bfloat162* LO = reinterpret_cast<__nv_bfloat162*>(g_xlo);
    HI[2*i]   = __nv_bfloat162(h0, h1);
    HI[2*i+1] = __nv_bfloat162(h2, h3);
    LO[2*i]   = __nv_bfloat162(__float2bfloat16(v.x - __bfloat162float(h0)),
                               __float2bfloat16(v.y - __bfloat162float(h1)));
    LO[2*i+1] = __nv_bfloat162(__float2bfloat16(v.z - __bfloat162float(h2)),
                               __float2bfloat16(v.w - __bfloat162float(h3)));
}

__global__ void conv_wkv_kernel(const float* __restrict__ kw, const float* __restrict__ vw)
{
    size_t i = (size_t)blockIdx.x * blockDim.x + threadIdx.x;
    size_t e = i * 4;
    int r = (int)(e >> 10), c = (int)(e & 1023);
    int h = r >> 7, r7 = r & 127;
    const float* src = (r7 < 64) ? (kw + ((size_t)(h*64 + r7)) * DD + c)
                                 : (vw + ((size_t)(h*64 + r7 - 64)) * DD + c);
    float4 v = *reinterpret_cast<const float4*>(src);
    __nv_bfloat16 h0 = __float2bfloat16(v.x), h1 = __float2bfloat16(v.y);
    __nv_bfloat16 h2 = __float2bfloat16(v.z), h3 = __float2bfloat16(v.w);
    __nv_bfloat162* HI = reinterpret_cast<__nv_bfloat162*>(g_wkvhi);
    __nv_bfloat162* LO = reinterpret_cast<__nv_bfloat162*>(g_wkvlo);
    HI[2*i]   = __nv_bfloat162(h0, h1);
    HI[2*i+1] = __nv_bfloat162(h2, h3);
    LO[2*i]   = __nv_bfloat162(__float2bfloat16(v.x - __bfloat162float(h0)),
                               __float2bfloat16(v.y - __bfloat162float(h1)));
    LO[2*i+1] = __nv_bfloat162(__float2bfloat16(v.z - __bfloat162float(h2)),
                               __float2bfloat16(v.w - __bfloat162float(h3)));
}

__global__ void conv_ow_kernel(const float* __restrict__ ow)
{
    size_t i = (size_t)blockIdx.x * blockDim.x + threadIdx.x;
    float4 v = reinterpret_cast<const float4*>(ow)[i];
    __nv_bfloat16 h0 = __float2bfloat16(v.x), h1 = __float2bfloat16(v.y);
    __nv_bfloat16 h2 = __float2bfloat16(v.z), h3 = __float2bfloat16(v.w);
    __nv_bfloat162* HI = reinterpret_cast<__nv_bfloat162*>(g_owhi);
    __nv_bfloat162* LO = reinterpret_cast<__nv_bfloat162*>(g_owlo);
    HI[2*i]   = __nv_bfloat162(h0, h1);
    HI[2*i+1] = __nv_bfloat162(h2, h3);
    LO[2*i]   = __nv_bfloat162(__float2bfloat16(v.x - __bfloat162float(h0)),
                               __float2bfloat16(v.y - __bfloat162float(h1)));
    LO[2*i+1] = __nv_bfloat162(__float2bfloat16(v.z - __bfloat162float(h2)),
                               __float2bfloat16(v.w - __bfloat162float(h3)));
}

// ---------------------------------------------------------------------------
// shared mainloop pieces
// ---------------------------------------------------------------------------
__device__ __forceinline__ void load_stage(
    const __nv_bfloat16* __restrict__ gAhi, const __nv_bfloat16* __restrict__ gAlo,
    const __nv_bfloat16* __restrict__ gBhi, const __nv_bfloat16* __restrict__ gBlo,
    int m0, int n0, int kc, uint32_t sbase, int t)
{
    #pragma unroll
    for (int i = 0; i < 2; ++i) {
        int e   = t + i * 256;          // 0..511
        int row = e >> 2;               // 0..127
        int c   = e & 3;                // 16B chunk within 64B
        uint32_t so = (uint32_t)row * ROWPITCH + (uint32_t)c * 16;
        size_t goA = ((size_t)(m0 + row) << 10) + (size_t)kc * KC + c * 8;
        size_t goB = ((size_t)(n0 + row) << 10) + (size_t)kc * KC + c * 8;
        CP_ASYNC(sbase + A_HI_OFF + so, gAhi + goA);
        CP_ASYNC(sbase + A_LO_OFF + so, gAlo + goA);
        CP_ASYNC(sbase + B_HI_OFF + so, gBhi + goB);
        CP_ASYNC(sbase + B_LO_OFF + so, gBlo + goB);
    }
}

__device__ __forceinline__ void compute_stage(uint32_t st, int m0w, int n0w, int lane,
                                              float acc[4][4][4])
{
    #pragma unroll
    for (int kh = 0; kh < 2; ++kh) {
        uint32_t ah[4][4], al[4][4];
        uint32_t aoffb = (uint32_t)(m0w + (lane & 15)) * ROWPITCH + kh * 32 + ((lane >> 4) << 4);
        #pragma unroll
        for (int mt = 0; mt < 4; ++mt) {
            uint32_t off = aoffb + mt * 16 * ROWPITCH;
            ldmx4(ah[mt], st + A_HI_OFF + off);
            ldmx4(al[mt], st + A_LO_OFF + off);
        }
        uint32_t bh[2][4], bl[2][4];
        uint32_t boffb = (uint32_t)(n0w + (lane & 7) + ((lane >> 4) << 3)) * ROWPITCH
                       + kh * 32 + ((lane & 8) << 1);
        #pragma unroll
        for (int bj = 0; bj < 2; ++bj) {
            uint32_t off = boffb + bj * 16 * ROWPITCH;
            ldmx4(bh[bj], st + B_HI_OFF + off);
            ldmx4(bl[bj], st + B_LO_OFF + off);
        }
        #pragma unroll
        for (int mt = 0; mt < 4; ++mt)
            #pragma unroll
            for (int nt = 0; nt < 4; ++nt) {
                const uint32_t* bfh = &bh[nt >> 1][(nt & 1) * 2];
                const uint32_t* bfl = &bl[nt >> 1][(nt & 1) * 2];
                mma16816(acc[mt][nt], ah[mt], bfh);
                mma16816(acc[mt][nt], ah[mt], bfl);
                mma16816(acc[mt][nt], al[mt], bfh);
            }
    }
}

// ---------------------------------------------------------------------------
// GEMM #1: C[16384,2048] = x @ Wkv^T (3x bf16 split) + fused ||k||, wv epilogue
// Block = 128 tokens x 128 cols (one head: 64 k-cols | 64 v-cols).
// ---------------------------------------------------------------------------
__global__ __launch_bounds__(256) void kv_gemm_kernel(
    const float* __restrict__ kb, const float* __restrict__ vb)
{
    extern __shared__ char sp[];
    __shared__ float s_kb[64], s_vb[64];
    const int t    = threadIdx.x;
    const int lane = t & 31;
    const int w    = t >> 5;
    const int m0w  = (w >> 2) * 64;
    const int n0w  = (w & 3) * 32;
    const int m0   = blockIdx.x * 128;
    const int h    = blockIdx.y;          // head
    const int n0   = h * 128;
    uint32_t sb = smem_u32(sp);

    if (t < 64)       s_kb[t]      = kb[h * 64 + t];
    else if (t < 128) s_vb[t - 64] = vb[h * 64 + t - 64];

    float acc[4][4][4];
    #pragma unroll
    for (int a = 0; a < 4; ++a)
        #pragma unroll
        for (int b = 0; b < 4; ++b)
            #pragma unroll
            for (int q = 0; q < 4; ++q) acc[a][b][q] = 0.f;

    load_stage(g_xhi, g_xlo, g_wkvhi, g_wkvlo, m0, n0, 0, sb + 0 * STAGE, t); CP_COMMIT();
    load_stage(g_xhi, g_xlo, g_wkvhi, g_wkvlo, m0, n0, 1, sb + 1 * STAGE, t); CP_COMMIT();

    for (int s = 0; s < NCH; ++s) {
        __syncthreads();
        if (s + 2 < NCH) {
            load_stage(g_xhi, g_xlo, g_wkvhi, g_wkvlo, m0, n0, s + 2, sb + ((s + 2) % 3) * STAGE, t);
            CP_COMMIT(); CP_WAIT2();
        } else if (s + 1 < NCH) { CP_WAIT1(); }
        else                    { CP_WAIT0(); }
        __syncthreads();
        compute_stage(sb + (s % 3) * STAGE, m0w, n0w, lane, acc);
    }
    __syncthreads();      // all warps done reading smem before epilogue reuse

    // dump accumulators to smem: 128 x 128 fp32, row pitch 132
    float* sC = reinterpret_cast<float*>(sp);
    #pragma unroll
    for (int mt = 0; mt < 4; ++mt)
        #pragma unroll
        for (int nt = 0; nt < 4; ++nt) {
            int r = m0w + mt * 16 + (lane >> 2);
            int c = n0w + nt * 8 + ((lane & 3) << 1);
            sC[r * 132 + c]           = acc[mt][nt][0];
            sC[r * 132 + c + 1]       = acc[mt][nt][1];
            sC[(r + 8) * 132 + c]     = acc[mt][nt][2];
            sC[(r + 8) * 132 + c + 1] = acc[mt][nt][3];
        }
    __syncthreads();

    if (t < 128) {
        const float* row = sC + t * 132;
        float ssq = 0.f;
        #pragma unroll
        for (int j = 0; j < 64; ++j) {
            float kv = row[j] + s_kb[j];
            ssq = fmaf(kv, kv, ssq);
        }
        float m = sqrtf(ssq);
        float* dst = g_wv + (size_t)(m0 + t) * DD + h * 64;
        #pragma unroll
        for (int j4 = 0; j4 < 16; ++j4) {
            float4 o;
            o.x = (row[64 + j4*4 + 0] + s_vb[j4*4 + 0]) * m;
            o.y = (row[64 + j4*4 + 1] + s_vb[j4*4 + 1]) * m;
            o.z = (row[64 + j4*4 + 2] + s_vb[j4*4 + 2]) * m;
            o.w = (row[64 + j4*4 + 3] + s_vb[j4*4 + 3]) * m;
            *reinterpret_cast<float4*>(dst + j4 * 4) = o;
        }
    }
}

// ---------------------------------------------------------------------------
// GEMM #2: R[2048,1024] = A @ ow^T + ob (same mainloop, direct epilogue)
// ---------------------------------------------------------------------------
__global__ __launch_bounds__(256) void out_gemm_kernel(const float* __restrict__ ob)
{
    extern __shared__ char sp[];
    __shared__ float s_ob[128];
    const int t    = threadIdx.x;
    const int lane = t & 31;
    const int w    = t >> 5;
    const int m0w  = (w >> 2) * 64;
    const int n0w  = (w & 3) * 32;
    const int m0   = blockIdx.x * 128;
    const int j0   = blockIdx.y * 128;
    uint32_t sb = smem_u32(sp);

    if (t < 128) s_ob[t] = ob[j0 + t];

    float acc[4][4][4];
    #pragma unroll
    for (int a = 0; a < 4; ++a)
        #pragma unroll
        for (int b = 0; b < 4; ++b)
            #pragma unroll
            for (int q = 0; q < 4; ++q) acc[a][b][q] = 0.f;

    load_stage(g_Ahi, g_Alo, g_owhi, g_owlo, m0, j0, 0, sb + 0 * STAGE, t); CP_COMMIT();
    load_stage(g_Ahi, g_Alo, g_owhi, g_owlo, m0, j0, 1, sb + 1 * STAGE, t); CP_COMMIT();

    for (int s = 0; s < NCH; ++s) {
        __syncthreads();
        if (s + 2 < NCH) {
            load_stage(g_Ahi, g_Alo, g_owhi, g_owlo, m0, j0, s + 2, sb + ((s + 2) % 3) * STAGE, t);
            CP_COMMIT(); CP_WAIT2();
        } else if (s + 1 < NCH) { CP_WAIT1(); }
        else                    { CP_WAIT0(); }
        __syncthreads();
        compute_stage(sb + (s % 3) * STAGE, m0w, n0w, lane, acc);
    }

    __syncthreads();
    #pragma unroll
    for (int mt = 0; mt < 4; ++mt)
        #pragma unroll
        for (int nt = 0; nt < 4; ++nt) {
            int r  = m0 + m0w + mt * 16 + (lane >> 2);
            int cl = n0w + nt * 8 + ((lane & 3) << 1);
            float2 o0 = { acc[mt][nt][0] + s_ob[cl], acc[mt][nt][1] + s_ob[cl + 1] };
            float2 o1 = { acc[mt][nt][2] + s_ob[cl], acc[mt][nt][3] + s_ob[cl + 1] };
            *reinterpret_cast<float2*>(g_R + (size_t)r * DD + j0 + cl) = o0;
            *reinterpret_cast<float2*>(g_R + (size_t)(r + 8) * DD + j0 + cl) = o1;
        }
}

// ---------------------------------------------------------------------------
// segment-sum into field
// ---------------------------------------------------------------------------
__global__ void field_kernel()
{
    int g  = blockIdx.x;
    int bh = blockIdx.y;
    int b  = bh >> 4, h = bh & 15;
    int d  = threadIdx.x;
    int n0 = (int)(((long long)g * 4095) / 511) - 2;
    if (n0 < 0) n0 = 0;
    float s = 0.f;
    for (int n = n0; n < n0 + 14 && n < NN; ++n) {
        if (bin_of(n) == g)
            s += g_wv[((size_t)(b * NN + n)) * DD + h * HDIM + d];
    }
    g_field[((size_t)bh * GG + g) * HDIM + d] = s;
}

// ---------------------------------------------------------------------------
// circular exp-kernel convolution (anchor + geometric recursion)
// ---------------------------------------------------------------------------
#define TAPS 144
__global__ void conv_kernel()
{
    extern __shared__ float sf[];
    __shared__ float wsh[TAPS];
    int bh = blockIdx.x;
    const float* F = g_field + (size_t)bh * GG * HDIM;
    for (int i = threadIdx.x; i < GG * HDIM; i += blockDim.x)
        sf[i] = F[i];
    if (threadIdx.x < TAPS) {
        float Z = 0.f;
        for (int dd = 256; dd >= 1; --dd) Z += expf(-(float)dd / 3.0f);
        Z += 1e-8f;
        wsh[threadIdx.x] = expf(-(float)(threadIdx.x + 1) / 3.0f) / Z;
    }
    __syncthreads();

    int d    = threadIdx.x & 63;
    int g0   = (threadIdx.x >> 6) * 64;
    int gtop = g0 + 63;

    float acc = 0.f;
    for (int j = TAPS - 1; j >= 0; --j)
        acc = fmaf(wsh[j], sf[((gtop + 257 + j) & 511) * HDIM + d], acc);

    float* out = g_conv + (size_t)bh * GG * HDIM;
    out[gtop * HDIM + d] = acc;

    const float a  = 0.7165313105737893f;
    const float w0 = wsh[0];
    float C = acc;
    for (int g = gtop - 1; g >= g0; --g) {
        C = fmaf(a, C, w0 * sf[((g + 257) & 511) * HDIM + d]);
        out[g * HDIM + d] = C;
    }
}

// ---------------------------------------------------------------------------
// repack conv (B,H,G,hd) -> A (B*G, D), split to bf16 hi/lo
// ---------------------------------------------------------------------------
__global__ void repack_kernel()
{
    int m = blockIdx.x;              // b*G + g
    int b = m >> 9, g = m & 511;
    for (int k = threadIdx.x; k < DD; k += blockDim.x) {
        int h = k >> 6, d = k & 63;
        float v = g_conv[(((size_t)(b * HH + h)) * GG + g) * HDIM + d];
        __nv_bfloat16 hi = __float2bfloat16(v);
        g_Ahi[(size_t)m * DD + k] = hi;
        g_Alo[(size_t)m * DD + k] = __float2bfloat16(v - __bfloat162float(hi));
    }
}

// ---------------------------------------------------------------------------
// scatter per-bin rows back to all tokens
// ---------------------------------------------------------------------------
__global__ void scatter_kernel(float* __restrict__ out)
{
    int idx = blockIdx.x * blockDim.x + threadIdx.x;
    int c4  = idx & 255;
    int tok = idx >> 8;
    int n   = tok & (NN - 1);
    int b   = tok >> 12;
    int g   = bin_of(n);
    reinterpret_cast<float4*>(out)[(size_t)tok * 256 + c4] =
        reinterpret_cast<const float4*>(g_R)[((size_t)(b * GG + g)) * 256 + c4];
}

// ---------------------------------------------------------------------------
extern "C" void kernel_launch(void* const* d_in, const int* in_sizes, int n_in,
                              void* d_out, int out_size)
{
    const float* x  = (const float*)d_in[0];
    // d_in[1], d_in[2] are q_w, q_b — unused by the reference output.
    const float* kw = (const float*)d_in[3];
    const float* kb = (const float*)d_in[4];
    const float* vw = (const float*)d_in[5];
    const float* vb = (const float*)d_in[6];
    const float* ow = (const float*)d_in[7];
    const float* ob = (const float*)d_in[8];
    float* out = (float*)d_out;

    cudaFuncSetAttribute(kv_gemm_kernel,  cudaFuncAttributeMaxDynamicSharedMemorySize, DSMEM);
    cudaFuncSetAttribute(out_gemm_kernel, cudaFuncAttributeMaxDynamicSharedMemorySize, DSMEM);
    cudaFuncSetAttribute(conv_kernel, cudaFuncAttributeMaxDynamicSharedMemorySize,
                         GG * HDIM * (int)sizeof(float));

    conv_x_kernel<<<(BNTOK * DD / 4) / 256, 256>>>(x);
    conv_wkv_kernel<<<(2048 * DD / 4) / 256, 256>>>(kw, vw);
    conv_ow_kernel<<<(DD * DD / 4) / 256, 256>>>(ow);

    kv_gemm_kernel<<<dim3(BNTOK / 128, HH), 256, DSMEM>>>(kb, vb);

    field_kernel<<<dim3(GG, BB * HH), 64>>>();
    conv_kernel<<<BB * HH, 512, GG * HDIM * sizeof(float)>>>();
    repack_kernel<<<BB * GG, 256>>>();

    out_gemm_kernel<<<dim3((BB * GG) / 128, DD / 128), 256, DSMEM>>>(ob);
    scatter_kernel<<<(BNTOK * 256) / 256, 256>>>(out);
}

// round 5
// speedup vs baseline: 2.2797x; 1.1571x over previous
#include <cuda_runtime.h>
#include <cuda_bf16.h>
#include <math.h>
#include <stdint.h>

#define BB 4
#define NN 4096
#define DD 1024
#define HH 16
#define HDIM 64
#define GG 512
#define BNTOK (BB*NN)

// ---------------- scratch (device globals; no allocations allowed) ----------
__device__ float g_wv[(size_t)BNTOK * DD];              // 64MB  wv = v * ||k||
__device__ float g_field[(size_t)BB * HH * GG * HDIM];  // 8MB
__device__ float g_conv[(size_t)BB * HH * GG * HDIM];   // 8MB
__device__ float g_R[(size_t)BB * GG * DD];             // 8MB  per-bin out rows

__device__ __nv_bfloat16 g_xhi[(size_t)BNTOK * DD];     // 32MB
__device__ __nv_bfloat16 g_xlo[(size_t)BNTOK * DD];     // 32MB
__device__ __nv_bfloat16 g_wkvhi[(size_t)2048 * DD];    // packed [k|v] per head
__device__ __nv_bfloat16 g_wkvlo[(size_t)2048 * DD];
__device__ __nv_bfloat16 g_owhi[(size_t)DD * DD];
__device__ __nv_bfloat16 g_owlo[(size_t)DD * DD];
__device__ __nv_bfloat16 g_Ahi[(size_t)BB * GG * DD];   // conv repacked, bf16 split
__device__ __nv_bfloat16 g_Alo[(size_t)BB * GG * DD];

// Replicates jnp: pos = (n/4095.0f)*511.0f ; int32 trunc ; clip
__device__ __forceinline__ int bin_of(int n) {
    float p = ((float)n / 4095.0f) * 511.0f;
    int g = (int)p;
    g = g < 0 ? 0 : g;
    return g > 511 ? 511 : g;
}

// ---------------- baseline-PTX tensor helpers (sm_80+, ok on compute_103) ---
__device__ __forceinline__ uint32_t smem_u32(const void* p) {
    uint32_t a;
    asm("{ .reg .u64 t; cvta.to.shared.u64 t, %1; cvt.u32.u64 %0, t; }" : "=r"(a) : "l"(p));
    return a;
}
__device__ __forceinline__ void ldmx4(uint32_t* r, uint32_t a) {
    asm volatile("ldmatrix.sync.aligned.m8n8.x4.shared.b16 {%0,%1,%2,%3}, [%4];"
        : "=r"(r[0]), "=r"(r[1]), "=r"(r[2]), "=r"(r[3]) : "r"(a));
}
__device__ __forceinline__ void mma16816(float* c, const uint32_t* a, const uint32_t* b) {
    asm volatile("mma.sync.aligned.m16n8k16.row.col.f32.bf16.bf16.f32 "
        "{%0,%1,%2,%3}, {%4,%5,%6,%7}, {%8,%9}, {%0,%1,%2,%3};"
        : "+f"(c[0]), "+f"(c[1]), "+f"(c[2]), "+f"(c[3])
        : "r"(a[0]), "r"(a[1]), "r"(a[2]), "r"(a[3]), "r"(b[0]), "r"(b[1]));
}
#define CP_ASYNC(d, s) asm volatile("cp.async.cg.shared.global [%0], [%1], 16;" :: "r"(d), "l"(s) : "memory")
#define CP_COMMIT()    asm volatile("cp.async.commit_group;" ::: "memory")
#define CP_WAIT1()     asm volatile("cp.async.wait_group 1;" ::: "memory")
#define CP_WAIT0()     asm volatile("cp.async.wait_group 0;" ::: "memory")

// GEMM tiling: block 128x128, 8 warps (2x4), warp tile 64x32, K chunk 32
// 2 smem stages x 40KB = 80KB -> 2 CTAs/SM (cross-CTA latency hiding)
#define KC       32
#define NCH      32                 // 1024 / 32
#define ROWPITCH 80                 // 64B row + 16B pad (conflict-free ldmatrix)
#define A_HI_OFF 0
#define A_LO_OFF 10240
#define B_HI_OFF 20480
#define B_LO_OFF 30720
#define STAGE    40960
#define DSMEM    (2*STAGE)          // 81920

// ---------------------------------------------------------------------------
// fp32 -> bf16 hi/lo split conversions
// ---------------------------------------------------------------------------
__global__ void conv_x_kernel(const float* __restrict__ x)
{
    size_t i = (size_t)blockIdx.x * blockDim.x + threadIdx.x;
    float4 v = reinterpret_cast<const float4*>(x)[i];
    __nv_bfloat16 h0 = __float2bfloat16(v.x), h1 = __float2bfloat16(v.y);
    __nv_bfloat16 h2 = __float2bfloat16(v.z), h3 = __float2bfloat16(v.w);
    __nv_bfloat162* HI = reinterpret_cast<__nv_bfloat162*>(g_xhi);
    __nv_bfloat162* LO = reinterpret_cast<__nv_bfloat162*>(g_xlo);
    HI[2*i]   = __nv_bfloat162(h0, h1);
    HI[2*i+1] = __nv_bfloat162(h2, h3);
    LO[2*i]   = __nv_bfloat162(__float2bfloat16(v.x - __bfloat162float(h0)),
                               __float2bfloat16(v.y - __bfloat162float(h1)));
    LO[2*i+1] = __nv_bfloat162(__float2bfloat16(v.z - __bfloat162float(h2)),
                               __float2bfloat16(v.w - __bfloat162float(h3)));
}

__global__ void conv_wkv_kernel(const float* __restrict__ kw, const float* __restrict__ vw)
{
    size_t i = (size_t)blockIdx.x * blockDim.x + threadIdx.x;
    size_t e = i * 4;
    int r = (int)(e >> 10), c = (int)(e & 1023);
    int h = r >> 7, r7 = r & 127;
    const float* src = (r7 < 64) ? (kw + ((size_t)(h*64 + r7)) * DD + c)
                                 : (vw + ((size_t)(h*64 + r7 - 64)) * DD + c);
    float4 v = *reinterpret_cast<const float4*>(src);
    __nv_bfloat16 h0 = __float2bfloat16(v.x), h1 = __float2bfloat16(v.y);
    __nv_bfloat16 h2 = __float2bfloat16(v.z), h3 = __float2bfloat16(v.w);
    __nv_bfloat162* HI = reinterpret_cast<__nv_bfloat162*>(g_wkvhi);
    __nv_bfloat162* LO = reinterpret_cast<__nv_bfloat162*>(g_wkvlo);
    HI[2*i]   = __nv_bfloat162(h0, h1);
    HI[2*i+1] = __nv_bfloat162(h2, h3);
    LO[2*i]   = __nv_bfloat162(__float2bfloat16(v.x - __bfloat162float(h0)),
                               __float2bfloat16(v.y - __bfloat162float(h1)));
    LO[2*i+1] = __nv_bfloat162(__float2bfloat16(v.z - __bfloat162float(h2)),
                               __float2bfloat16(v.w - __bfloat162float(h3)));
}

__global__ void conv_ow_kernel(const float* __restrict__ ow)
{
    size_t i = (size_t)blockIdx.x * blockDim.x + threadIdx.x;
    float4 v = reinterpret_cast<const float4*>(ow)[i];
    __nv_bfloat16 h0 = __float2bfloat16(v.x), h1 = __float2bfloat16(v.y);
    __nv_bfloat16 h2 = __float2bfloat16(v.z), h3 = __float2bfloat16(v.w);
    __nv_bfloat162* HI = reinterpret_cast<__nv_bfloat162*>(g_owhi);
    __nv_bfloat162* LO = reinterpret_cast<__nv_bfloat162*>(g_owlo);
    HI[2*i]   = __nv_bfloat162(h0, h1);
    HI[2*i+1] = __nv_bfloat162(h2, h3);
    LO[2*i]   = __nv_bfloat162(__float2bfloat16(v.x - __bfloat162float(h0)),
                               __float2bfloat16(v.y - __bfloat162float(h1)));
    LO[2*i+1] = __nv_bfloat162(__float2bfloat16(v.z - __bfloat162float(h2)),
                               __float2bfloat16(v.w - __bfloat162float(h3)));
}

// ---------------------------------------------------------------------------
// shared mainloop pieces
// ---------------------------------------------------------------------------
__device__ __forceinline__ void load_stage(
    const __nv_bfloat16* __restrict__ gAhi, const __nv_bfloat16* __restrict__ gAlo,
    const __nv_bfloat16* __restrict__ gBhi, const __nv_bfloat16* __restrict__ gBlo,
    int m0, int n0, int kc, uint32_t sbase, int t)
{
    #pragma unroll
    for (int i = 0; i < 2; ++i) {
        int e   = t + i * 256;          // 0..511
        int row = e >> 2;               // 0..127
        int c   = e & 3;                // 16B chunk within 64B
        uint32_t so = (uint32_t)row * ROWPITCH + (uint32_t)c * 16;
        size_t goA = ((size_t)(m0 + row) << 10) + (size_t)kc * KC + c * 8;
        size_t goB = ((size_t)(n0 + row) << 10) + (size_t)kc * KC + c * 8;
        CP_ASYNC(sbase + A_HI_OFF + so, gAhi + goA);
        CP_ASYNC(sbase + A_LO_OFF + so, gAlo + goA);
        CP_ASYNC(sbase + B_HI_OFF + so, gBhi + goB);
        CP_ASYNC(sbase + B_LO_OFF + so, gBlo + goB);
    }
}

__device__ __forceinline__ void compute_stage(uint32_t st, int m0w, int n0w, int lane,
                                              float acc[4][4][4])
{
    #pragma unroll
    for (int kh = 0; kh < 2; ++kh) {
        uint32_t ah[4][4], al[4][4];
        uint32_t aoffb = (uint32_t)(m0w + (lane & 15)) * ROWPITCH + kh * 32 + ((lane >> 4) << 4);
        #pragma unroll
        for (int mt = 0; mt < 4; ++mt) {
            uint32_t off = aoffb + mt * 16 * ROWPITCH;
            ldmx4(ah[mt], st + A_HI_OFF + off);
            ldmx4(al[mt], st + A_LO_OFF + off);
        }
        uint32_t bh[2][4], bl[2][4];
        uint32_t boffb = (uint32_t)(n0w + (lane & 7) + ((lane >> 4) << 3)) * ROWPITCH
                       + kh * 32 + ((lane & 8) << 1);
        #pragma unroll
        for (int bj = 0; bj < 2; ++bj) {
            uint32_t off = boffb + bj * 16 * ROWPITCH;
            ldmx4(bh[bj], st + B_HI_OFF + off);
            ldmx4(bl[bj], st + B_LO_OFF + off);
        }
        #pragma unroll
        for (int mt = 0; mt < 4; ++mt)
            #pragma unroll
            for (int nt = 0; nt < 4; ++nt) {
                const uint32_t* bfh = &bh[nt >> 1][(nt & 1) * 2];
                const uint32_t* bfl = &bl[nt >> 1][(nt & 1) * 2];
                mma16816(acc[mt][nt], ah[mt], bfh);
                mma16816(acc[mt][nt], ah[mt], bfl);
                mma16816(acc[mt][nt], al[mt], bfh);
            }
    }
}

// ---------------------------------------------------------------------------
// GEMM #1: C[16384,2048] = x @ Wkv^T (3x bf16 split) + fused ||k||, wv epilogue
// Block = 128 tokens x 128 cols (one head: 64 k-cols | 64 v-cols).
// ---------------------------------------------------------------------------
__global__ __launch_bounds__(256, 2) void kv_gemm_kernel(
    const float* __restrict__ kb, const float* __restrict__ vb)
{
    extern __shared__ char sp[];
    __shared__ float s_kb[64], s_vb[64];
    const int t    = threadIdx.x;
    const int lane = t & 31;
    const int w    = t >> 5;
    const int m0w  = (w >> 2) * 64;
    const int n0w  = (w & 3) * 32;
    const int m0   = blockIdx.x * 128;
    const int h    = blockIdx.y;          // head
    const int n0   = h * 128;
    uint32_t sb = smem_u32(sp);

    if (t < 64)       s_kb[t]      = kb[h * 64 + t];
    else if (t < 128) s_vb[t - 64] = vb[h * 64 + t - 64];

    float acc[4][4][4];
    #pragma unroll
    for (int a = 0; a < 4; ++a)
        #pragma unroll
        for (int b = 0; b < 4; ++b)
            #pragma unroll
            for (int q = 0; q < 4; ++q) acc[a][b][q] = 0.f;

    load_stage(g_xhi, g_xlo, g_wkvhi, g_wkvlo, m0, n0, 0, sb, t); CP_COMMIT();

    for (int s = 0; s < NCH; ++s) {
        __syncthreads();   // previous compute done before overwriting its buffer
        if (s + 1 < NCH) {
            load_stage(g_xhi, g_xlo, g_wkvhi, g_wkvlo, m0, n0, s + 1,
                       sb + ((s + 1) & 1) * STAGE, t);
            CP_COMMIT(); CP_WAIT1();
        } else { CP_WAIT0(); }
        __syncthreads();
        compute_stage(sb + (s & 1) * STAGE, m0w, n0w, lane, acc);
    }
    __syncthreads();      // all warps done reading smem before epilogue reuse

    // dump accumulators to smem: 128 x 128 fp32, row pitch 132
    float* sC = reinterpret_cast<float*>(sp);
    #pragma unroll
    for (int mt = 0; mt < 4; ++mt)
        #pragma unroll
        for (int nt = 0; nt < 4; ++nt) {
            int r = m0w + mt * 16 + (lane >> 2);
            int c = n0w + nt * 8 + ((lane & 3) << 1);
            sC[r * 132 + c]           = acc[mt][nt][0];
            sC[r * 132 + c + 1]       = acc[mt][nt][1];
            sC[(r + 8) * 132 + c]     = acc[mt][nt][2];
            sC[(r + 8) * 132 + c + 1] = acc[mt][nt][3];
        }
    __syncthreads();

    if (t < 128) {
        const float* row = sC + t * 132;
        float ssq = 0.f;
        #pragma unroll
        for (int j = 0; j < 64; ++j) {
            float kv = row[j] + s_kb[j];
            ssq = fmaf(kv, kv, ssq);
        }
        float m = sqrtf(ssq);
        float* dst = g_wv + (size_t)(m0 + t) * DD + h * 64;
        #pragma unroll
        for (int j4 = 0; j4 < 16; ++j4) {
            float4 o;
            o.x = (row[64 + j4*4 + 0] + s_vb[j4*4 + 0]) * m;
            o.y = (row[64 + j4*4 + 1] + s_vb[j4*4 + 1]) * m;
            o.z = (row[64 + j4*4 + 2] + s_vb[j4*4 + 2]) * m;
            o.w = (row[64 + j4*4 + 3] + s_vb[j4*4 + 3]) * m;
            *reinterpret_cast<float4*>(dst + j4 * 4) = o;
        }
    }
}

// ---------------------------------------------------------------------------
// GEMM #2: R[2048,1024] = A @ ow^T + ob (same mainloop, direct epilogue)
// ---------------------------------------------------------------------------
__global__ __launch_bounds__(256, 2) void out_gemm_kernel(const float* __restrict__ ob)
{
    extern __shared__ char sp[];
    __shared__ float s_ob[128];
    const int t    = threadIdx.x;
    const int lane = t & 31;
    const int w    = t >> 5;
    const int m0w  = (w >> 2) * 64;
    const int n0w  = (w & 3) * 32;
    const int m0   = blockIdx.x * 128;
    const int j0   = blockIdx.y * 128;
    uint32_t sb = smem_u32(sp);

    if (t < 128) s_ob[t] = ob[j0 + t];

    float acc[4][4][4];
    #pragma unroll
    for (int a = 0; a < 4; ++a)
        #pragma unroll
        for (int b = 0; b < 4; ++b)
            #pragma unroll
            for (int q = 0; q < 4; ++q) acc[a][b][q] = 0.f;

    load_stage(g_Ahi, g_Alo, g_owhi, g_owlo, m0, j0, 0, sb, t); CP_COMMIT();

    for (int s = 0; s < NCH; ++s) {
        __syncthreads();
        if (s + 1 < NCH) {
            load_stage(g_Ahi, g_Alo, g_owhi, g_owlo, m0, j0, s + 1,
                       sb + ((s + 1) & 1) * STAGE, t);
            CP_COMMIT(); CP_WAIT1();
        } else { CP_WAIT0(); }
        __syncthreads();
        compute_stage(sb + (s & 1) * STAGE, m0w, n0w, lane, acc);
    }

    __syncthreads();
    #pragma unroll
    for (int mt = 0; mt < 4; ++mt)
        #pragma unroll
        for (int nt = 0; nt < 4; ++nt) {
            int r  = m0 + m0w + mt * 16 + (lane >> 2);
            int cl = n0w + nt * 8 + ((lane & 3) << 1);
            float2 o0 = { acc[mt][nt][0] + s_ob[cl], acc[mt][nt][1] + s_ob[cl + 1] };
            float2 o1 = { acc[mt][nt][2] + s_ob[cl], acc[mt][nt][3] + s_ob[cl + 1] };
            *reinterpret_cast<float2*>(g_R + (size_t)r * DD + j0 + cl) = o0;
            *reinterpret_cast<float2*>(g_R + (size_t)(r + 8) * DD + j0 + cl) = o1;
        }
}

// ---------------------------------------------------------------------------
// segment-sum into field
// ---------------------------------------------------------------------------
__global__ void field_kernel()
{
    int g  = blockIdx.x;
    int bh = blockIdx.y;
    int b  = bh >> 4, h = bh & 15;
    int d  = threadIdx.x;
    int n0 = (int)(((long long)g * 4095) / 511) - 2;
    if (n0 < 0) n0 = 0;
    float s = 0.f;
    for (int n = n0; n < n0 + 14 && n < NN; ++n) {
        if (bin_of(n) == g)
            s += g_wv[((size_t)(b * NN + n)) * DD + h * HDIM + d];
    }
    g_field[((size_t)bh * GG + g) * HDIM + d] = s;
}

// ---------------------------------------------------------------------------
// circular exp-kernel convolution (anchor + geometric recursion)
// ---------------------------------------------------------------------------
#define TAPS 144
__global__ void conv_kernel()
{
    extern __shared__ float sf[];
    __shared__ float wsh[TAPS];
    int bh = blockIdx.x;
    const float* F = g_field + (size_t)bh * GG * HDIM;
    for (int i = threadIdx.x; i < GG * HDIM; i += blockDim.x)
        sf[i] = F[i];
    if (threadIdx.x < TAPS) {
        float Z = 0.f;
        for (int dd = 256; dd >= 1; --dd) Z += expf(-(float)dd / 3.0f);
        Z += 1e-8f;
        wsh[threadIdx.x] = expf(-(float)(threadIdx.x + 1) / 3.0f) / Z;
    }
    __syncthreads();

    int d    = threadIdx.x & 63;
    int g0   = (threadIdx.x >> 6) * 64;
    int gtop = g0 + 63;

    float acc = 0.f;
    for (int j = TAPS - 1; j >= 0; --j)
        acc = fmaf(wsh[j], sf[((gtop + 257 + j) & 511) * HDIM + d], acc);

    float* out = g_conv + (size_t)bh * GG * HDIM;
    out[gtop * HDIM + d] = acc;

    const float a  = 0.7165313105737893f;
    const float w0 = wsh[0];
    float C = acc;
    for (int g = gtop - 1; g >= g0; --g) {
        C = fmaf(a, C, w0 * sf[((g + 257) & 511) * HDIM + d]);
        out[g * HDIM + d] = C;
    }
}

// ---------------------------------------------------------------------------
// repack conv (B,H,G,hd) -> A (B*G, D), split to bf16 hi/lo
// ---------------------------------------------------------------------------
__global__ void repack_kernel()
{
    int m = blockIdx.x;              // b*G + g
    int b = m >> 9, g = m & 511;
    for (int k = threadIdx.x; k < DD; k += blockDim.x) {
        int h = k >> 6, d = k & 63;
        float v = g_conv[(((size_t)(b * HH + h)) * GG + g) * HDIM + d];
        __nv_bfloat16 hi = __float2bfloat16(v);
        g_Ahi[(size_t)m * DD + k] = hi;
        g_Alo[(size_t)m * DD + k] = __float2bfloat16(v - __bfloat162float(hi));
    }
}

// ---------------------------------------------------------------------------
// scatter per-bin rows back to all tokens
// ---------------------------------------------------------------------------
__global__ void scatter_kernel(float* __restrict__ out)
{
    int idx = blockIdx.x * blockDim.x + threadIdx.x;
    int c4  = idx & 255;
    int tok = idx >> 8;
    int n   = tok & (NN - 1);
    int b   = tok >> 12;
    int g   = bin_of(n);
    reinterpret_cast<float4*>(out)[(size_t)tok * 256 + c4] =
        reinterpret_cast<const float4*>(g_R)[((size_t)(b * GG + g)) * 256 + c4];
}

// ---------------------------------------------------------------------------
extern "C" void kernel_launch(void* const* d_in, const int* in_sizes, int n_in,
                              void* d_out, int out_size)
{
    const float* x  = (const float*)d_in[0];
    // d_in[1], d_in[2] are q_w, q_b — unused by the reference output.
    const float* kw = (const float*)d_in[3];
    const float* kb = (const float*)d_in[4];
    const float* vw = (const float*)d_in[5];
    const float* vb = (const float*)d_in[6];
    const float* ow = (const float*)d_in[7];
    const float* ob = (const float*)d_in[8];
    float* out = (float*)d_out;

    cudaFuncSetAttribute(kv_gemm_kernel,  cudaFuncAttributeMaxDynamicSharedMemorySize, DSMEM);
    cudaFuncSetAttribute(out_gemm_kernel, cudaFuncAttributeMaxDynamicSharedMemorySize, DSMEM);
    cudaFuncSetAttribute(conv_kernel, cudaFuncAttributeMaxDynamicSharedMemorySize,
                         GG * HDIM * (int)sizeof(float));

    conv_x_kernel<<<(BNTOK * DD / 4) / 256, 256>>>(x);
    conv_wkv_kernel<<<(2048 * DD / 4) / 256, 256>>>(kw, vw);
    conv_ow_kernel<<<(DD * DD / 4) / 256, 256>>>(ow);

    kv_gemm_kernel<<<dim3(BNTOK / 128, HH), 256, DSMEM>>>(kb, vb);

    field_kernel<<<dim3(GG, BB * HH), 64>>>();
    conv_kernel<<<BB * HH, 512, GG * HDIM * sizeof(float)>>>();
    repack_kernel<<<BB * GG, 256>>>();

    out_gemm_kernel<<<dim3((BB * GG) / 128, DD / 128), 256, DSMEM>>>(ob);
    scatter_kernel<<<(BNTOK * 256) / 256, 256>>>(out);
}

// round 6
// speedup vs baseline: 2.4677x; 1.0825x over previous
#include <cuda_runtime.h>
#include <cuda_bf16.h>
#include <math.h>
#include <stdint.h>

#define BB 4
#define NN 4096
#define DD 1024
#define HH 16
#define HDIM 64
#define GG 512
#define BNTOK (BB*NN)

// ---------------- scratch (device globals; no allocations allowed) ----------
__device__ float g_wv[(size_t)BNTOK * DD];              // 64MB  wv = v * ||k||
__device__ float g_field[(size_t)BB * HH * GG * HDIM];  // 8MB
__device__ float g_conv[(size_t)BB * HH * GG * HDIM];   // 8MB
__device__ float g_R[(size_t)BB * GG * DD];             // 8MB  per-bin out rows

__device__ __nv_bfloat16 g_xhi[(size_t)BNTOK * DD];     // 32MB
__device__ __nv_bfloat16 g_xlo[(size_t)BNTOK * DD];     // 32MB
__device__ __nv_bfloat16 g_wkvhi[(size_t)2048 * DD];    // packed [k|v] per head
__device__ __nv_bfloat16 g_wkvlo[(size_t)2048 * DD];
__device__ __nv_bfloat16 g_owhi[(size_t)DD * DD];
__device__ __nv_bfloat16 g_owlo[(size_t)DD * DD];
__device__ __nv_bfloat16 g_Ahi[(size_t)BB * GG * DD];   // conv repacked, bf16 split
__device__ __nv_bfloat16 g_Alo[(size_t)BB * GG * DD];

// Replicates jnp: pos = (n/4095.0f)*511.0f ; int32 trunc ; clip
__device__ __forceinline__ int bin_of(int n) {
    float p = ((float)n / 4095.0f) * 511.0f;
    int g = (int)p;
    g = g < 0 ? 0 : g;
    return g > 511 ? 511 : g;
}

// ---------------- baseline-PTX tensor helpers (sm_80+, ok on compute_103) ---
__device__ __forceinline__ uint32_t smem_u32(const void* p) {
    uint32_t a;
    asm("{ .reg .u64 t; cvta.to.shared.u64 t, %1; cvt.u32.u64 %0, t; }" : "=r"(a) : "l"(p));
    return a;
}
__device__ __forceinline__ void ldmx4(uint32_t* r, uint32_t a) {
    asm volatile("ldmatrix.sync.aligned.m8n8.x4.shared.b16 {%0,%1,%2,%3}, [%4];"
        : "=r"(r[0]), "=r"(r[1]), "=r"(r[2]), "=r"(r[3]) : "r"(a));
}
__device__ __forceinline__ void mma16816(float* c, const uint32_t* a, const uint32_t* b) {
    asm volatile("mma.sync.aligned.m16n8k16.row.col.f32.bf16.bf16.f32 "
        "{%0,%1,%2,%3}, {%4,%5,%6,%7}, {%8,%9}, {%0,%1,%2,%3};"
        : "+f"(c[0]), "+f"(c[1]), "+f"(c[2]), "+f"(c[3])
        : "r"(a[0]), "r"(a[1]), "r"(a[2]), "r"(a[3]), "r"(b[0]), "r"(b[1]));
}
#define CP_ASYNC(d, s) asm volatile("cp.async.cg.shared.global [%0], [%1], 16;" :: "r"(d), "l"(s) : "memory")
#define CP_COMMIT()    asm volatile("cp.async.commit_group;" ::: "memory")
#define CP_WAIT1()     asm volatile("cp.async.wait_group 1;" ::: "memory")
#define CP_WAIT0()     asm volatile("cp.async.wait_group 0;" ::: "memory")

// GEMM tiling: block 128x128, 8 warps (2x4), warp tile 64x32, K chunk 32.
// Tile row layout: [hi 64B | lo 64B] = 128B with Swizzle<3,4,3> (XOR, no pad).
// 3 stages x 32KB = 96KB/CTA -> 2 CTAs/SM. Single __syncthreads per K-step.
#define KC       32
#define NCH      32                 // 1024 / 32
#define B_OFF    16384
#define STAGE    32768
#define DSMEM    (3*STAGE)          // 98304

// swizzled byte offset for (row, logical 16B-chunk c in 0..7): hi c=0..3, lo c=4..7
__device__ __forceinline__ uint32_t swz(uint32_t row, uint32_t c) {
    return row * 128u + ((c ^ (row & 7u)) << 4);
}

// ---------------------------------------------------------------------------
// fp32 -> bf16 hi/lo split conversions
// ---------------------------------------------------------------------------
__global__ void conv_x_kernel(const float* __restrict__ x)
{
    size_t i = (size_t)blockIdx.x * blockDim.x + threadIdx.x;
    float4 v = reinterpret_cast<const float4*>(x)[i];
    __nv_bfloat16 h0 = __float2bfloat16(v.x), h1 = __float2bfloat16(v.y);
    __nv_bfloat16 h2 = __float2bfloat16(v.z), h3 = __float2bfloat16(v.w);
    __nv_bfloat162* HI = reinterpret_cast<__nv_bfloat162*>(g_xhi);
    __nv_bfloat162* LO = reinterpret_cast<__nv_bfloat162*>(g_xlo);
    HI[2*i]   = __nv_bfloat162(h0, h1);
    HI[2*i+1] = __nv_bfloat162(h2, h3);
    LO[2*i]   = __nv_bfloat162(__float2bfloat16(v.x - __bfloat162float(h0)),
                               __float2bfloat16(v.y - __bfloat162float(h1)));
    LO[2*i+1] = __nv_bfloat162(__float2bfloat16(v.z - __bfloat162float(h2)),
                               __float2bfloat16(v.w - __bfloat162float(h3)));
}

__global__ void conv_wkv_kernel(const float* __restrict__ kw, const float* __restrict__ vw)
{
    size_t i = (size_t)blockIdx.x * blockDim.x + threadIdx.x;
    size_t e = i * 4;
    int r = (int)(e >> 10), c = (int)(e & 1023);
    int h = r >> 7, r7 = r & 127;
    const float* src = (r7 < 64) ? (kw + ((size_t)(h*64 + r7)) * DD + c)
                                 : (vw + ((size_t)(h*64 + r7 - 64)) * DD + c);
    float4 v = *reinterpret_cast<const float4*>(src);
    __nv_bfloat16 h0 = __float2bfloat16(v.x), h1 = __float2bfloat16(v.y);
    __nv_bfloat16 h2 = __float2bfloat16(v.z), h3 = __float2bfloat16(v.w);
    __nv_bfloat162* HI = reinterpret_cast<__nv_bfloat162*>(g_wkvhi);
    __nv_bfloat162* LO = reinterpret_cast<__nv_bfloat162*>(g_wkvlo);
    HI[2*i]   = __nv_bfloat162(h0, h1);
    HI[2*i+1] = __nv_bfloat162(h2, h3);
    LO[2*i]   = __nv_bfloat162(__float2bfloat16(v.x - __bfloat162float(h0)),
                               __float2bfloat16(v.y - __bfloat162float(h1)));
    LO[2*i+1] = __nv_bfloat162(__float2bfloat16(v.z - __bfloat162float(h2)),
                               __float2bfloat16(v.w - __bfloat162float(h3)));
}

__global__ void conv_ow_kernel(const float* __restrict__ ow)
{
    size_t i = (size_t)blockIdx.x * blockDim.x + threadIdx.x;
    float4 v = reinterpret_cast<const float4*>(ow)[i];
    __nv_bfloat16 h0 = __float2bfloat16(v.x), h1 = __float2bfloat16(v.y);
    __nv_bfloat16 h2 = __float2bfloat16(v.z), h3 = __float2bfloat16(v.w);
    __nv_bfloat162* HI = reinterpret_cast<__nv_bfloat162*>(g_owhi);
    __nv_bfloat162* LO = reinterpret_cast<__nv_bfloat162*>(g_owlo);
    HI[2*i]   = __nv_bfloat162(h0, h1);
    HI[2*i+1] = __nv_bfloat162(h2, h3);
    LO[2*i]   = __nv_bfloat162(__float2bfloat16(v.x - __bfloat162float(h0)),
                               __float2bfloat16(v.y - __bfloat162float(h1)));
    LO[2*i+1] = __nv_bfloat162(__float2bfloat16(v.z - __bfloat162float(h2)),
                               __float2bfloat16(v.w - __bfloat162float(h3)));
}

// ---------------------------------------------------------------------------
// shared mainloop pieces
// ---------------------------------------------------------------------------
__device__ __forceinline__ void load_stage(
    const __nv_bfloat16* __restrict__ gAhi, const __nv_bfloat16* __restrict__ gAlo,
    const __nv_bfloat16* __restrict__ gBhi, const __nv_bfloat16* __restrict__ gBlo,
    int m0, int n0, int kc, uint32_t sbase, int t)
{
    #pragma unroll
    for (int i = 0; i < 4; ++i) {        // A: 128 rows x 8 chunks of 16B
        int e   = t + i * 256;           // 0..1023
        int row = e >> 3;
        int c   = e & 7;
        const __nv_bfloat16* src = ((c < 4) ? gAhi : gAlo)
            + (((size_t)(m0 + row)) << 10) + (size_t)kc * KC + (c & 3) * 8;
        CP_ASYNC(sbase + swz(row, c), src);
    }
    #pragma unroll
    for (int i = 0; i < 4; ++i) {        // B
        int e   = t + i * 256;
        int row = e >> 3;
        int c   = e & 7;
        const __nv_bfloat16* src = ((c < 4) ? gBhi : gBlo)
            + (((size_t)(n0 + row)) << 10) + (size_t)kc * KC + (c & 3) * 8;
        CP_ASYNC(sbase + B_OFF + swz(row, c), src);
    }
}

__device__ __forceinline__ void compute_stage(uint32_t st, int m0w, int n0w, int lane,
                                              float acc[4][4][4])
{
    #pragma unroll
    for (int kh = 0; kh < 2; ++kh) {
        uint32_t ah[4][4], al[4][4];
        uint32_t arow = (uint32_t)(m0w + (lane & 15));
        uint32_t ac   = (uint32_t)(kh * 2 + (lane >> 4));     // 0..3 (hi)
        #pragma unroll
        for (int mt = 0; mt < 4; ++mt) {
            uint32_t r = arow + mt * 16;
            ldmx4(ah[mt], st + swz(r, ac));
            ldmx4(al[mt], st + swz(r, ac + 4));
        }
        uint32_t bh[2][4], bl[2][4];
        uint32_t brow = (uint32_t)(n0w + (lane & 7) + ((lane >> 4) << 3));
        uint32_t bc   = (uint32_t)(kh * 2 + ((lane & 8) >> 3));
        #pragma unroll
        for (int bj = 0; bj < 2; ++bj) {
            uint32_t r = brow + bj * 16;
            ldmx4(bh[bj], st + B_OFF + swz(r, bc));
            ldmx4(bl[bj], st + B_OFF + swz(r, bc + 4));
        }
        #pragma unroll
        for (int mt = 0; mt < 4; ++mt)
            #pragma unroll
            for (int nt = 0; nt < 4; ++nt) {
                const uint32_t* bfh = &bh[nt >> 1][(nt & 1) * 2];
                const uint32_t* bfl = &bl[nt >> 1][(nt & 1) * 2];
                mma16816(acc[mt][nt], ah[mt], bfh);
                mma16816(acc[mt][nt], ah[mt], bfl);
                mma16816(acc[mt][nt], al[mt], bfh);
            }
    }
}

// ---------------------------------------------------------------------------
// GEMM #1: C[16384,2048] = x @ Wkv^T (3x bf16 split) + fused ||k||, wv epilogue
// ---------------------------------------------------------------------------
__global__ __launch_bounds__(256, 2) void kv_gemm_kernel(
    const float* __restrict__ kb, const float* __restrict__ vb)
{
    extern __shared__ char sp[];
    __shared__ float s_kb[64], s_vb[64];
    const int t    = threadIdx.x;
    const int lane = t & 31;
    const int w    = t >> 5;
    const int m0w  = (w >> 2) * 64;
    const int n0w  = (w & 3) * 32;
    const int m0   = blockIdx.x * 128;
    const int h    = blockIdx.y;          // head
    const int n0   = h * 128;
    uint32_t sb = smem_u32(sp);

    if (t < 64)       s_kb[t]      = kb[h * 64 + t];
    else if (t < 128) s_vb[t - 64] = vb[h * 64 + t - 64];

    float acc[4][4][4];
    #pragma unroll
    for (int a = 0; a < 4; ++a)
        #pragma unroll
        for (int b = 0; b < 4; ++b)
            #pragma unroll
            for (int q = 0; q < 4; ++q) acc[a][b][q] = 0.f;

    load_stage(g_xhi, g_xlo, g_wkvhi, g_wkvlo, m0, n0, 0, sb,         t); CP_COMMIT();
    load_stage(g_xhi, g_xlo, g_wkvhi, g_wkvlo, m0, n0, 1, sb + STAGE, t); CP_COMMIT();

    for (int s = 0; s < NCH; ++s) {
        if (s + 2 < NCH) { CP_WAIT1(); } else { CP_WAIT0(); }
        __syncthreads();                 // stage s visible; compute(s-1) done
        if (s + 2 < NCH) {
            load_stage(g_xhi, g_xlo, g_wkvhi, g_wkvlo, m0, n0, s + 2,
                       sb + ((s + 2) % 3) * STAGE, t);
            CP_COMMIT();
        }
        compute_stage(sb + (s % 3) * STAGE, m0w, n0w, lane, acc);
    }
    __syncthreads();      // all warps done reading smem before epilogue reuse

    // dump accumulators to smem: 128 x 128 fp32, row pitch 132
    float* sC = reinterpret_cast<float*>(sp);
    #pragma unroll
    for (int mt = 0; mt < 4; ++mt)
        #pragma unroll
        for (int nt = 0; nt < 4; ++nt) {
            int r = m0w + mt * 16 + (lane >> 2);
            int c = n0w + nt * 8 + ((lane & 3) << 1);
            sC[r * 132 + c]           = acc[mt][nt][0];
            sC[r * 132 + c + 1]       = acc[mt][nt][1];
            sC[(r + 8) * 132 + c]     = acc[mt][nt][2];
            sC[(r + 8) * 132 + c + 1] = acc[mt][nt][3];
        }
    __syncthreads();

    if (t < 128) {
        const float* row = sC + t * 132;
        float ssq = 0.f;
        #pragma unroll
        for (int j = 0; j < 64; ++j) {
            float kv = row[j] + s_kb[j];
            ssq = fmaf(kv, kv, ssq);
        }
        float m = sqrtf(ssq);
        float* dst = g_wv + (size_t)(m0 + t) * DD + h * 64;
        #pragma unroll
        for (int j4 = 0; j4 < 16; ++j4) {
            float4 o;
            o.x = (row[64 + j4*4 + 0] + s_vb[j4*4 + 0]) * m;
            o.y = (row[64 + j4*4 + 1] + s_vb[j4*4 + 1]) * m;
            o.z = (row[64 + j4*4 + 2] + s_vb[j4*4 + 2]) * m;
            o.w = (row[64 + j4*4 + 3] + s_vb[j4*4 + 3]) * m;
            *reinterpret_cast<float4*>(dst + j4 * 4) = o;
        }
    }
}

// ---------------------------------------------------------------------------
// GEMM #2: R[2048,1024] = A @ ow^T + ob (same mainloop, direct epilogue)
// ---------------------------------------------------------------------------
__global__ __launch_bounds__(256, 2) void out_gemm_kernel(const float* __restrict__ ob)
{
    extern __shared__ char sp[];
    __shared__ float s_ob[128];
    const int t    = threadIdx.x;
    const int lane = t & 31;
    const int w    = t >> 5;
    const int m0w  = (w >> 2) * 64;
    const int n0w  = (w & 3) * 32;
    const int m0   = blockIdx.x * 128;
    const int j0   = blockIdx.y * 128;
    uint32_t sb = smem_u32(sp);

    if (t < 128) s_ob[t] = ob[j0 + t];

    float acc[4][4][4];
    #pragma unroll
    for (int a = 0; a < 4; ++a)
        #pragma unroll
        for (int b = 0; b < 4; ++b)
            #pragma unroll
            for (int q = 0; q < 4; ++q) acc[a][b][q] = 0.f;

    load_stage(g_Ahi, g_Alo, g_owhi, g_owlo, m0, j0, 0, sb,         t); CP_COMMIT();
    load_stage(g_Ahi, g_Alo, g_owhi, g_owlo, m0, j0, 1, sb + STAGE, t); CP_COMMIT();

    for (int s = 0; s < NCH; ++s) {
        if (s + 2 < NCH) { CP_WAIT1(); } else { CP_WAIT0(); }
        __syncthreads();
        if (s + 2 < NCH) {
            load_stage(g_Ahi, g_Alo, g_owhi, g_owlo, m0, j0, s + 2,
                       sb + ((s + 2) % 3) * STAGE, t);
            CP_COMMIT();
        }
        compute_stage(sb + (s % 3) * STAGE, m0w, n0w, lane, acc);
    }

    __syncthreads();
    #pragma unroll
    for (int mt = 0; mt < 4; ++mt)
        #pragma unroll
        for (int nt = 0; nt < 4; ++nt) {
            int r  = m0 + m0w + mt * 16 + (lane >> 2);
            int cl = n0w + nt * 8 + ((lane & 3) << 1);
            float2 o0 = { acc[mt][nt][0] + s_ob[cl], acc[mt][nt][1] + s_ob[cl + 1] };
            float2 o1 = { acc[mt][nt][2] + s_ob[cl], acc[mt][nt][3] + s_ob[cl + 1] };
            *reinterpret_cast<float2*>(g_R + (size_t)r * DD + j0 + cl) = o0;
            *reinterpret_cast<float2*>(g_R + (size_t)(r + 8) * DD + j0 + cl) = o1;
        }
}

// ---------------------------------------------------------------------------
// segment-sum into field
// ---------------------------------------------------------------------------
__global__ void field_kernel()
{
    int g  = blockIdx.x;
    int bh = blockIdx.y;
    int b  = bh >> 4, h = bh & 15;
    int d  = threadIdx.x;
    int n0 = (int)(((long long)g * 4095) / 511) - 2;
    if (n0 < 0) n0 = 0;
    float s = 0.f;
    for (int n = n0; n < n0 + 14 && n < NN; ++n) {
        if (bin_of(n) == g)
            s += g_wv[((size_t)(b * NN + n)) * DD + h * HDIM + d];
    }
    g_field[((size_t)bh * GG + g) * HDIM + d] = s;
}

// ---------------------------------------------------------------------------
// circular exp-kernel convolution (anchor + geometric recursion)
// ---------------------------------------------------------------------------
#define TAPS 144
__global__ void conv_kernel()
{
    extern __shared__ float sf[];
    __shared__ float wsh[TAPS];
    int bh = blockIdx.x;
    const float* F = g_field + (size_t)bh * GG * HDIM;
    for (int i = threadIdx.x; i < GG * HDIM; i += blockDim.x)
        sf[i] = F[i];
    if (threadIdx.x < TAPS) {
        float Z = 0.f;
        for (int dd = 256; dd >= 1; --dd) Z += expf(-(float)dd / 3.0f);
        Z += 1e-8f;
        wsh[threadIdx.x] = expf(-(float)(threadIdx.x + 1) / 3.0f) / Z;
    }
    __syncthreads();

    int d    = threadIdx.x & 63;
    int g0   = (threadIdx.x >> 6) * 64;
    int gtop = g0 + 63;

    float acc = 0.f;
    for (int j = TAPS - 1; j >= 0; --j)
        acc = fmaf(wsh[j], sf[((gtop + 257 + j) & 511) * HDIM + d], acc);

    float* out = g_conv + (size_t)bh * GG * HDIM;
    out[gtop * HDIM + d] = acc;

    const float a  = 0.7165313105737893f;
    const float w0 = wsh[0];
    float C = acc;
    for (int g = gtop - 1; g >= g0; --g) {
        C = fmaf(a, C, w0 * sf[((g + 257) & 511) * HDIM + d]);
        out[g * HDIM + d] = C;
    }
}

// ---------------------------------------------------------------------------
// repack conv (B,H,G,hd) -> A (B*G, D), split to bf16 hi/lo
// ---------------------------------------------------------------------------
__global__ void repack_kernel()
{
    int m = blockIdx.x;              // b*G + g
    int b = m >> 9, g = m & 511;
    for (int k = threadIdx.x; k < DD; k += blockDim.x) {
        int h = k >> 6, d = k & 63;
        float v = g_conv[(((size_t)(b * HH + h)) * GG + g) * HDIM + d];
        __nv_bfloat16 hi = __float2bfloat16(v);
        g_Ahi[(size_t)m * DD + k] = hi;
        g_Alo[(size_t)m * DD + k] = __float2bfloat16(v - __bfloat162float(hi));
    }
}

// ---------------------------------------------------------------------------
// scatter per-bin rows back to all tokens
// ---------------------------------------------------------------------------
__global__ void scatter_kernel(float* __restrict__ out)
{
    int idx = blockIdx.x * blockDim.x + threadIdx.x;
    int c4  = idx & 255;
    int tok = idx >> 8;
    int n   = tok & (NN - 1);
    int b   = tok >> 12;
    int g   = bin_of(n);
    reinterpret_cast<float4*>(out)[(size_t)tok * 256 + c4] =
        reinterpret_cast<const float4*>(g_R)[((size_t)(b * GG + g)) * 256 + c4];
}

// ---------------------------------------------------------------------------
extern "C" void kernel_launch(void* const* d_in, const int* in_sizes, int n_in,
                              void* d_out, int out_size)
{
    const float* x  = (const float*)d_in[0];
    // d_in[1], d_in[2] are q_w, q_b — unused by the reference output.
    const float* kw = (const float*)d_in[3];
    const float* kb = (const float*)d_in[4];
    const float* vw = (const float*)d_in[5];
    const float* vb = (const float*)d_in[6];
    const float* ow = (const float*)d_in[7];
    const float* ob = (const float*)d_in[8];
    float* out = (float*)d_out;

    cudaFuncSetAttribute(kv_gemm_kernel,  cudaFuncAttributeMaxDynamicSharedMemorySize, DSMEM);
    cudaFuncSetAttribute(out_gemm_kernel, cudaFuncAttributeMaxDynamicSharedMemorySize, DSMEM);
    cudaFuncSetAttribute(conv_kernel, cudaFuncAttributeMaxDynamicSharedMemorySize,
                         GG * HDIM * (int)sizeof(float));

    conv_x_kernel<<<(BNTOK * DD / 4) / 256, 256>>>(x);
    conv_wkv_kernel<<<(2048 * DD / 4) / 256, 256>>>(kw, vw);
    conv_ow_kernel<<<(DD * DD / 4) / 256, 256>>>(ow);

    kv_gemm_kernel<<<dim3(BNTOK / 128, HH), 256, DSMEM>>>(kb, vb);

    field_kernel<<<dim3(GG, BB * HH), 64>>>();
    conv_kernel<<<BB * HH, 512, GG * HDIM * sizeof(float)>>>();
    repack_kernel<<<BB * GG, 256>>>();

    out_gemm_kernel<<<dim3((BB * GG) / 128, DD / 128), 256, DSMEM>>>(ob);
    scatter_kernel<<<(BNTOK * 256) / 256, 256>>>(out);
}

// round 7
// speedup vs baseline: 3.5720x; 1.4475x over previous
#include <cuda_runtime.h>
#include <cuda_fp16.h>
#include <math.h>
#include <stdint.h>

#define BB 4
#define NN 4096
#define DD 1024
#define HH 16
#define HDIM 64
#define GG 512
#define BNTOK (BB*NN)

// ---------------- scratch (device globals; no allocations allowed) ----------
__device__ float g_wv[(size_t)BNTOK * DD];              // 64MB  wv = v * ||k||
__device__ float g_field[(size_t)BB * HH * GG * HDIM];  // 8MB
__device__ float g_conv[(size_t)BB * HH * GG * HDIM];   // 8MB
__device__ float g_R[(size_t)BB * GG * DD];             // 8MB  per-bin out rows

// fp16 operands: activations split 2-term (hi+lo, exact to 2^-22),
// weights single fp16 (error 2^-11 -> ~2.5e-4 per GEMM, gate is 1e-3)
__device__ __half g_xhi[(size_t)BNTOK * DD];            // 32MB
__device__ __half g_xlo[(size_t)BNTOK * DD];            // 32MB
__device__ __half g_wkv[(size_t)2048 * DD];             // 4MB  packed [k|v] per head
__device__ __half g_ow [(size_t)DD * DD];               // 2MB
__device__ __half g_Ahi[(size_t)BB * GG * DD];          // conv repacked, fp16 split
__device__ __half g_Alo[(size_t)BB * GG * DD];

// Replicates jnp: pos = (n/4095.0f)*511.0f ; int32 trunc ; clip
__device__ __forceinline__ int bin_of(int n) {
    float p = ((float)n / 4095.0f) * 511.0f;
    int g = (int)p;
    g = g < 0 ? 0 : g;
    return g > 511 ? 511 : g;
}

// ---------------- baseline-PTX tensor helpers (sm_80+, ok on compute_103) ---
__device__ __forceinline__ uint32_t smem_u32(const void* p) {
    uint32_t a;
    asm("{ .reg .u64 t; cvta.to.shared.u64 t, %1; cvt.u32.u64 %0, t; }" : "=r"(a) : "l"(p));
    return a;
}
__device__ __forceinline__ void ldmx4(uint32_t* r, uint32_t a) {
    asm volatile("ldmatrix.sync.aligned.m8n8.x4.shared.b16 {%0,%1,%2,%3}, [%4];"
        : "=r"(r[0]), "=r"(r[1]), "=r"(r[2]), "=r"(r[3]) : "r"(a));
}
__device__ __forceinline__ void mma16816(float* c, const uint32_t* a, const uint32_t* b) {
    asm volatile("mma.sync.aligned.m16n8k16.row.col.f32.f16.f16.f32 "
        "{%0,%1,%2,%3}, {%4,%5,%6,%7}, {%8,%9}, {%0,%1,%2,%3};"
        : "+f"(c[0]), "+f"(c[1]), "+f"(c[2]), "+f"(c[3])
        : "r"(a[0]), "r"(a[1]), "r"(a[2]), "r"(a[3]), "r"(b[0]), "r"(b[1]));
}
#define CP_ASYNC(d, s) asm volatile("cp.async.cg.shared.global [%0], [%1], 16;" :: "r"(d), "l"(s) : "memory")
#define CP_COMMIT()    asm volatile("cp.async.commit_group;" ::: "memory")
#define CP_WAIT1()     asm volatile("cp.async.wait_group 1;" ::: "memory")
#define CP_WAIT0()     asm volatile("cp.async.wait_group 0;" ::: "memory")

// GEMM tiling: block 128x128, 8 warps (2x4), warp tile 64x32, K chunk 64.
// Stage: A_hi 16KB | A_lo 16KB | B 16KB = 48KB; 2 stages = 96KB -> 2 CTAs/SM.
// 128B rows (64 fp16 = one K-chunk of 64), Swizzle<3,4,3>.
#define KC       64
#define NCH      16                 // 1024 / 64
#define A_LO_OFF 16384
#define B_OFF    32768
#define STAGE    49152
#define DSMEM    (2*STAGE)          // 98304

// swizzled byte offset for (row, 16B-chunk c in 0..7)
__device__ __forceinline__ uint32_t swz(uint32_t row, uint32_t c) {
    return row * 128u + ((c ^ (row & 7u)) << 4);
}

// ---------------------------------------------------------------------------
// fp32 -> fp16 conversions
// ---------------------------------------------------------------------------
__global__ void conv_x_kernel(const float* __restrict__ x)
{
    size_t i = (size_t)blockIdx.x * blockDim.x + threadIdx.x;
    float4 v = reinterpret_cast<const float4*>(x)[i];
    __half h0 = __float2half(v.x), h1 = __float2half(v.y);
    __half h2 = __float2half(v.z), h3 = __float2half(v.w);
    __half2* HI = reinterpret_cast<__half2*>(g_xhi);
    __half2* LO = reinterpret_cast<__half2*>(g_xlo);
    HI[2*i]   = __half2(h0, h1);
    HI[2*i+1] = __half2(h2, h3);
    LO[2*i]   = __half2(__float2half(v.x - __half2float(h0)),
                        __float2half(v.y - __half2float(h1)));
    LO[2*i+1] = __half2(__float2half(v.z - __half2float(h2)),
                        __float2half(v.w - __half2float(h3)));
}

// pack kw/vw into [2048,1024] fp16: row r -> head h=r>>7; r7<64: kw row, else vw
__global__ void conv_wkv_kernel(const float* __restrict__ kw, const float* __restrict__ vw)
{
    size_t i = (size_t)blockIdx.x * blockDim.x + threadIdx.x;   // over 2048*1024/4
    size_t e = i * 4;
    int r = (int)(e >> 10), c = (int)(e & 1023);
    int h = r >> 7, r7 = r & 127;
    const float* src = (r7 < 64) ? (kw + ((size_t)(h*64 + r7)) * DD + c)
                                 : (vw + ((size_t)(h*64 + r7 - 64)) * DD + c);
    float4 v = *reinterpret_cast<const float4*>(src);
    __half2* W = reinterpret_cast<__half2*>(g_wkv);
    W[2*i]   = __half2(__float2half(v.x), __float2half(v.y));
    W[2*i+1] = __half2(__float2half(v.z), __float2half(v.w));
}

__global__ void conv_ow_kernel(const float* __restrict__ ow)
{
    size_t i = (size_t)blockIdx.x * blockDim.x + threadIdx.x;
    float4 v = reinterpret_cast<const float4*>(ow)[i];
    __half2* W = reinterpret_cast<__half2*>(g_ow);
    W[2*i]   = __half2(__float2half(v.x), __float2half(v.y));
    W[2*i+1] = __half2(__float2half(v.z), __float2half(v.w));
}

// ---------------------------------------------------------------------------
// shared mainloop pieces
// ---------------------------------------------------------------------------
__device__ __forceinline__ void load_stage(
    const __half* __restrict__ gAhi, const __half* __restrict__ gAlo,
    const __half* __restrict__ gB,
    int m0, int n0, int kc, uint32_t sbase, int t)
{
    #pragma unroll
    for (int i = 0; i < 4; ++i) {        // A_hi: 128 rows x 8 chunks of 16B
        int e = t + i * 256;
        int row = e >> 3, c = e & 7;
        CP_ASYNC(sbase + swz(row, c),
                 gAhi + (((size_t)(m0 + row)) << 10) + (size_t)kc * KC + c * 8);
    }
    #pragma unroll
    for (int i = 0; i < 4; ++i) {        // A_lo
        int e = t + i * 256;
        int row = e >> 3, c = e & 7;
        CP_ASYNC(sbase + A_LO_OFF + swz(row, c),
                 gAlo + (((size_t)(m0 + row)) << 10) + (size_t)kc * KC + c * 8);
    }
    #pragma unroll
    for (int i = 0; i < 4; ++i) {        // B (hi only)
        int e = t + i * 256;
        int row = e >> 3, c = e & 7;
        CP_ASYNC(sbase + B_OFF + swz(row, c),
                 gB + (((size_t)(n0 + row)) << 10) + (size_t)kc * KC + c * 8);
    }
}

__device__ __forceinline__ void compute_stage(uint32_t st, int m0w, int n0w, int lane,
                                              float acc[4][4][4])
{
    #pragma unroll
    for (int kh = 0; kh < 4; ++kh) {     // 4 x k16 within KC=64
        uint32_t ah[4][4], al[4][4];
        uint32_t arow = (uint32_t)(m0w + (lane & 15));
        uint32_t ac   = (uint32_t)(kh * 2 + (lane >> 4));     // 0..7
        #pragma unroll
        for (int mt = 0; mt < 4; ++mt) {
            uint32_t r = arow + mt * 16;
            ldmx4(ah[mt], st + swz(r, ac));
            ldmx4(al[mt], st + A_LO_OFF + swz(r, ac));
        }
        uint32_t bh[2][4];
        uint32_t brow = (uint32_t)(n0w + (lane & 7) + ((lane >> 4) << 3));
        uint32_t bc   = (uint32_t)(kh * 2 + ((lane & 8) >> 3));
        #pragma unroll
        for (int bj = 0; bj < 2; ++bj)
            ldmx4(bh[bj], st + B_OFF + swz(brow + bj * 16, bc));
        #pragma unroll
        for (int mt = 0; mt < 4; ++mt)
            #pragma unroll
            for (int nt = 0; nt < 4; ++nt) {
                const uint32_t* bf = &bh[nt >> 1][(nt & 1) * 2];
                mma16816(acc[mt][nt], ah[mt], bf);
                mma16816(acc[mt][nt], al[mt], bf);
            }
    }
}

// ---------------------------------------------------------------------------
// GEMM #1: C[16384,2048] = x @ Wkv^T (fp16 2-term) + fused ||k||, wv epilogue
// ---------------------------------------------------------------------------
__global__ __launch_bounds__(256, 2) void kv_gemm_kernel(
    const float* __restrict__ kb, const float* __restrict__ vb)
{
    extern __shared__ char sp[];
    __shared__ float s_kb[64], s_vb[64];
    const int t    = threadIdx.x;
    const int lane = t & 31;
    const int w    = t >> 5;
    const int m0w  = (w >> 2) * 64;
    const int n0w  = (w & 3) * 32;
    const int m0   = blockIdx.x * 128;
    const int h    = blockIdx.y;          // head
    const int n0   = h * 128;
    uint32_t sb = smem_u32(sp);

    if (t < 64)       s_kb[t]      = kb[h * 64 + t];
    else if (t < 128) s_vb[t - 64] = vb[h * 64 + t - 64];

    float acc[4][4][4];
    #pragma unroll
    for (int a = 0; a < 4; ++a)
        #pragma unroll
        for (int b = 0; b < 4; ++b)
            #pragma unroll
            for (int q = 0; q < 4; ++q) acc[a][b][q] = 0.f;

    load_stage(g_xhi, g_xlo, g_wkv, m0, n0, 0, sb, t); CP_COMMIT();

    for (int s = 0; s < NCH; ++s) {
        if (s + 1 < NCH) {
            load_stage(g_xhi, g_xlo, g_wkv, m0, n0, s + 1, sb + ((s + 1) & 1) * STAGE, t);
            CP_COMMIT(); CP_WAIT1();
        } else { CP_WAIT0(); }
        __syncthreads();
        compute_stage(sb + (s & 1) * STAGE, m0w, n0w, lane, acc);
        __syncthreads();
    }

    // dump accumulators to smem: 128 x 128 fp32, row pitch 132
    float* sC = reinterpret_cast<float*>(sp);
    #pragma unroll
    for (int mt = 0; mt < 4; ++mt)
        #pragma unroll
        for (int nt = 0; nt < 4; ++nt) {
            int r = m0w + mt * 16 + (lane >> 2);
            int c = n0w + nt * 8 + ((lane & 3) << 1);
            sC[r * 132 + c]           = acc[mt][nt][0];
            sC[r * 132 + c + 1]       = acc[mt][nt][1];
            sC[(r + 8) * 132 + c]     = acc[mt][nt][2];
            sC[(r + 8) * 132 + c + 1] = acc[mt][nt][3];
        }
    __syncthreads();

    if (t < 128) {
        const float* row = sC + t * 132;
        float ssq = 0.f;
        #pragma unroll
        for (int j = 0; j < 64; ++j) {
            float kv = row[j] + s_kb[j];
            ssq = fmaf(kv, kv, ssq);
        }
        float m = sqrtf(ssq);
        float* dst = g_wv + (size_t)(m0 + t) * DD + h * 64;
        #pragma unroll
        for (int j4 = 0; j4 < 16; ++j4) {
            float4 o;
            o.x = (row[64 + j4*4 + 0] + s_vb[j4*4 + 0]) * m;
            o.y = (row[64 + j4*4 + 1] + s_vb[j4*4 + 1]) * m;
            o.z = (row[64 + j4*4 + 2] + s_vb[j4*4 + 2]) * m;
            o.w = (row[64 + j4*4 + 3] + s_vb[j4*4 + 3]) * m;
            *reinterpret_cast<float4*>(dst + j4 * 4) = o;
        }
    }
}

// ---------------------------------------------------------------------------
// GEMM #2: R[2048,1024] = A @ ow^T + ob (same mainloop, direct epilogue)
// ---------------------------------------------------------------------------
__global__ __launch_bounds__(256, 2) void out_gemm_kernel(const float* __restrict__ ob)
{
    extern __shared__ char sp[];
    __shared__ float s_ob[128];
    const int t    = threadIdx.x;
    const int lane = t & 31;
    const int w    = t >> 5;
    const int m0w  = (w >> 2) * 64;
    const int n0w  = (w & 3) * 32;
    const int m0   = blockIdx.x * 128;
    const int j0   = blockIdx.y * 128;
    uint32_t sb = smem_u32(sp);

    if (t < 128) s_ob[t] = ob[j0 + t];

    float acc[4][4][4];
    #pragma unroll
    for (int a = 0; a < 4; ++a)
        #pragma unroll
        for (int b = 0; b < 4; ++b)
            #pragma unroll
            for (int q = 0; q < 4; ++q) acc[a][b][q] = 0.f;

    load_stage(g_Ahi, g_Alo, g_ow, m0, j0, 0, sb, t); CP_COMMIT();

    for (int s = 0; s < NCH; ++s) {
        if (s + 1 < NCH) {
            load_stage(g_Ahi, g_Alo, g_ow, m0, j0, s + 1, sb + ((s + 1) & 1) * STAGE, t);
            CP_COMMIT(); CP_WAIT1();
        } else { CP_WAIT0(); }
        __syncthreads();
        compute_stage(sb + (s & 1) * STAGE, m0w, n0w, lane, acc);
        __syncthreads();
    }

    #pragma unroll
    for (int mt = 0; mt < 4; ++mt)
        #pragma unroll
        for (int nt = 0; nt < 4; ++nt) {
            int r  = m0 + m0w + mt * 16 + (lane >> 2);
            int cl = n0w + nt * 8 + ((lane & 3) << 1);
            float2 o0 = { acc[mt][nt][0] + s_ob[cl], acc[mt][nt][1] + s_ob[cl + 1] };
            float2 o1 = { acc[mt][nt][2] + s_ob[cl], acc[mt][nt][3] + s_ob[cl + 1] };
            *reinterpret_cast<float2*>(g_R + (size_t)r * DD + j0 + cl) = o0;
            *reinterpret_cast<float2*>(g_R + (size_t)(r + 8) * DD + j0 + cl) = o1;
        }
}

// ---------------------------------------------------------------------------
// segment-sum into field
// ---------------------------------------------------------------------------
__global__ void field_kernel()
{
    int g  = blockIdx.x;
    int bh = blockIdx.y;
    int b  = bh >> 4, h = bh & 15;
    int d  = threadIdx.x;
    int n0 = (int)(((long long)g * 4095) / 511) - 2;
    if (n0 < 0) n0 = 0;
    float s = 0.f;
    for (int n = n0; n < n0 + 14 && n < NN; ++n) {
        if (bin_of(n) == g)
            s += g_wv[((size_t)(b * NN + n)) * DD + h * HDIM + d];
    }
    g_field[((size_t)bh * GG + g) * HDIM + d] = s;
}

// ---------------------------------------------------------------------------
// circular exp-kernel convolution (anchor + geometric recursion)
// ---------------------------------------------------------------------------
#define TAPS 144
__global__ void conv_kernel()
{
    extern __shared__ float sf[];
    __shared__ float wsh[TAPS];
    int bh = blockIdx.x;
    const float* F = g_field + (size_t)bh * GG * HDIM;
    for (int i = threadIdx.x; i < GG * HDIM; i += blockDim.x)
        sf[i] = F[i];
    if (threadIdx.x < TAPS) {
        float Z = 0.f;
        for (int dd = 256; dd >= 1; --dd) Z += expf(-(float)dd / 3.0f);
        Z += 1e-8f;
        wsh[threadIdx.x] = expf(-(float)(threadIdx.x + 1) / 3.0f) / Z;
    }
    __syncthreads();

    int d    = threadIdx.x & 63;
    int g0   = (threadIdx.x >> 6) * 64;
    int gtop = g0 + 63;

    float acc = 0.f;
    for (int j = TAPS - 1; j >= 0; --j)
        acc = fmaf(wsh[j], sf[((gtop + 257 + j) & 511) * HDIM + d], acc);

    float* out = g_conv + (size_t)bh * GG * HDIM;
    out[gtop * HDIM + d] = acc;

    const float a  = 0.7165313105737893f;
    const float w0 = wsh[0];
    float C = acc;
    for (int g = gtop - 1; g >= g0; --g) {
        C = fmaf(a, C, w0 * sf[((g + 257) & 511) * HDIM + d]);
        out[g * HDIM + d] = C;
    }
}

// ---------------------------------------------------------------------------
// repack conv (B,H,G,hd) -> A (B*G, D), split to fp16 hi/lo
// ---------------------------------------------------------------------------
__global__ void repack_kernel()
{
    int m = blockIdx.x;              // b*G + g
    int b = m >> 9, g = m & 511;
    for (int k = threadIdx.x; k < DD; k += blockDim.x) {
        int h = k >> 6, d = k & 63;
        float v = g_conv[(((size_t)(b * HH + h)) * GG + g) * HDIM + d];
        __half hi = __float2half(v);
        g_Ahi[(size_t)m * DD + k] = hi;
        g_Alo[(size_t)m * DD + k] = __float2half(v - __half2float(hi));
    }
}

// ---------------------------------------------------------------------------
// scatter per-bin rows back to all tokens
// ---------------------------------------------------------------------------
__global__ void scatter_kernel(float* __restrict__ out)
{
    int idx = blockIdx.x * blockDim.x + threadIdx.x;
    int c4  = idx & 255;
    int tok = idx >> 8;
    int n   = tok & (NN - 1);
    int b   = tok >> 12;
    int g   = bin_of(n);
    reinterpret_cast<float4*>(out)[(size_t)tok * 256 + c4] =
        reinterpret_cast<const float4*>(g_R)[((size_t)(b * GG + g)) * 256 + c4];
}

// ---------------------------------------------------------------------------
extern "C" void kernel_launch(void* const* d_in, const int* in_sizes, int n_in,
                              void* d_out, int out_size)
{
    const float* x  = (const float*)d_in[0];
    // d_in[1], d_in[2] are q_w, q_b — unused by the reference output.
    const float* kw = (const float*)d_in[3];
    const float* kb = (const float*)d_in[4];
    const float* vw = (const float*)d_in[5];
    const float* vb = (const float*)d_in[6];
    const float* ow = (const float*)d_in[7];
    const float* ob = (const float*)d_in[8];
    float* out = (float*)d_out;

    cudaFuncSetAttribute(kv_gemm_kernel,  cudaFuncAttributeMaxDynamicSharedMemorySize, DSMEM);
    cudaFuncSetAttribute(out_gemm_kernel, cudaFuncAttributeMaxDynamicSharedMemorySize, DSMEM);
    cudaFuncSetAttribute(conv_kernel, cudaFuncAttributeMaxDynamicSharedMemorySize,
                         GG * HDIM * (int)sizeof(float));

    conv_x_kernel<<<(BNTOK * DD / 4) / 256, 256>>>(x);
    conv_wkv_kernel<<<(2048 * DD / 4) / 256, 256>>>(kw, vw);
    conv_ow_kernel<<<(DD * DD / 4) / 256, 256>>>(ow);

    kv_gemm_kernel<<<dim3(BNTOK / 128, HH), 256, DSMEM>>>(kb, vb);

    field_kernel<<<dim3(GG, BB * HH), 64>>>();
    conv_kernel<<<BB * HH, 512, GG * HDIM * sizeof(float)>>>();
    repack_kernel<<<BB * GG, 256>>>();

    out_gemm_kernel<<<dim3((BB * GG) / 128, DD / 128), 256, DSMEM>>>(ob);
    scatter_kernel<<<(BNTOK * 256) / 256, 256>>>(out);
}

// round 8
// speedup vs baseline: 5.4443x; 1.5242x over previous
#include <cuda_runtime.h>
#include <cuda_fp16.h>
#include <math.h>
#include <stdint.h>

#define BB 4
#define NN 4096
#define DD 1024
#define HH 16
#define HDIM 64
#define GG 512
#define BNTOK (BB*NN)

// ---------------- scratch (device globals; no allocations allowed) ----------
__device__ float g_wv[(size_t)BNTOK * DD];              // 64MB  wv = v * ||k||
__device__ float g_field[(size_t)BB * HH * GG * HDIM];  // 8MB

// fp16 operands (plain fp16: measured error budget allows it, see notes)
__device__ __half g_x  [(size_t)BNTOK * DD];            // 32MB
__device__ __half g_wkv[(size_t)2048 * DD];             // 4MB  packed [k|v] per head
__device__ __half g_ow [(size_t)DD * DD];               // 2MB
__device__ __half g_A  [(size_t)BB * GG * DD];          // 4MB  conv result, repacked

// Replicates jnp: pos = (n/4095.0f)*511.0f ; int32 trunc ; clip
__device__ __forceinline__ int bin_of(int n) {
    float p = ((float)n / 4095.0f) * 511.0f;
    int g = (int)p;
    g = g < 0 ? 0 : g;
    return g > 511 ? 511 : g;
}

// ---------------- baseline-PTX tensor helpers (sm_80+, ok on compute_103) ---
__device__ __forceinline__ uint32_t smem_u32(const void* p) {
    uint32_t a;
    asm("{ .reg .u64 t; cvta.to.shared.u64 t, %1; cvt.u32.u64 %0, t; }" : "=r"(a) : "l"(p));
    return a;
}
__device__ __forceinline__ void ldmx4(uint32_t* r, uint32_t a) {
    asm volatile("ldmatrix.sync.aligned.m8n8.x4.shared.b16 {%0,%1,%2,%3}, [%4];"
        : "=r"(r[0]), "=r"(r[1]), "=r"(r[2]), "=r"(r[3]) : "r"(a));
}
__device__ __forceinline__ void mma16816(float* c, const uint32_t* a, const uint32_t* b) {
    asm volatile("mma.sync.aligned.m16n8k16.row.col.f32.f16.f16.f32 "
        "{%0,%1,%2,%3}, {%4,%5,%6,%7}, {%8,%9}, {%0,%1,%2,%3};"
        : "+f"(c[0]), "+f"(c[1]), "+f"(c[2]), "+f"(c[3])
        : "r"(a[0]), "r"(a[1]), "r"(a[2]), "r"(a[3]), "r"(b[0]), "r"(b[1]));
}
#define CP_ASYNC(d, s) asm volatile("cp.async.cg.shared.global [%0], [%1], 16;" :: "r"(d), "l"(s) : "memory")
#define CP_COMMIT()    asm volatile("cp.async.commit_group;" ::: "memory")
#define CP_WAIT1()     asm volatile("cp.async.wait_group 1;" ::: "memory")
#define CP_WAIT0()     asm volatile("cp.async.wait_group 0;" ::: "memory")

// GEMM tiling: block 128x128, 8 warps (2x4), warp tile 64x32, K chunk 64.
// Stage: A 16KB | B 16KB = 32KB; 3 stages = 96KB -> 2 CTAs/SM.
// Single __syncthreads per K-step, 2-deep cp.async lookahead.
// 128B rows (64 fp16 = one K-chunk), Swizzle<3,4,3>.
#define KC       64
#define NCH      16                 // 1024 / 64
#define B_OFF    16384
#define STAGE    32768
#define DSMEM    (3*STAGE)          // 98304

// swizzled byte offset for (row, 16B-chunk c in 0..7)
__device__ __forceinline__ uint32_t swz(uint32_t row, uint32_t c) {
    return row * 128u + ((c ^ (row & 7u)) << 4);
}

// ---------------------------------------------------------------------------
// fp32 -> fp16 conversions
// ---------------------------------------------------------------------------
__global__ void conv_x_kernel(const float* __restrict__ x)
{
    size_t i = (size_t)blockIdx.x * blockDim.x + threadIdx.x;
    float4 v = reinterpret_cast<const float4*>(x)[i];
    __half2* X = reinterpret_cast<__half2*>(g_x);
    X[2*i]   = __half2(__float2half(v.x), __float2half(v.y));
    X[2*i+1] = __half2(__float2half(v.z), __float2half(v.w));
}

// pack kw/vw into [2048,1024] fp16: row r -> head h=r>>7; r7<64: kw row, else vw
__global__ void conv_wkv_kernel(const float* __restrict__ kw, const float* __restrict__ vw)
{
    size_t i = (size_t)blockIdx.x * blockDim.x + threadIdx.x;   // over 2048*1024/4
    size_t e = i * 4;
    int r = (int)(e >> 10), c = (int)(e & 1023);
    int h = r >> 7, r7 = r & 127;
    const float* src = (r7 < 64) ? (kw + ((size_t)(h*64 + r7)) * DD + c)
                                 : (vw + ((size_t)(h*64 + r7 - 64)) * DD + c);
    float4 v = *reinterpret_cast<const float4*>(src);
    __half2* W = reinterpret_cast<__half2*>(g_wkv);
    W[2*i]   = __half2(__float2half(v.x), __float2half(v.y));
    W[2*i+1] = __half2(__float2half(v.z), __float2half(v.w));
}

__global__ void conv_ow_kernel(const float* __restrict__ ow)
{
    size_t i = (size_t)blockIdx.x * blockDim.x + threadIdx.x;
    float4 v = reinterpret_cast<const float4*>(ow)[i];
    __half2* W = reinterpret_cast<__half2*>(g_ow);
    W[2*i]   = __half2(__float2half(v.x), __float2half(v.y));
    W[2*i+1] = __half2(__float2half(v.z), __float2half(v.w));
}

// ---------------------------------------------------------------------------
// shared mainloop pieces (single-term fp16)
// ---------------------------------------------------------------------------
__device__ __forceinline__ void load_stage(
    const __half* __restrict__ gA, const __half* __restrict__ gB,
    int m0, int n0, int kc, uint32_t sbase, int t)
{
    #pragma unroll
    for (int i = 0; i < 4; ++i) {        // A: 128 rows x 8 chunks of 16B
        int e = t + i * 256;
        int row = e >> 3, c = e & 7;
        CP_ASYNC(sbase + swz(row, c),
                 gA + (((size_t)(m0 + row)) << 10) + (size_t)kc * KC + c * 8);
    }
    #pragma unroll
    for (int i = 0; i < 4; ++i) {        // B
        int e = t + i * 256;
        int row = e >> 3, c = e & 7;
        CP_ASYNC(sbase + B_OFF + swz(row, c),
                 gB + (((size_t)(n0 + row)) << 10) + (size_t)kc * KC + c * 8);
    }
}

__device__ __forceinline__ void compute_stage(uint32_t st, int m0w, int n0w, int lane,
                                              float acc[4][4][4])
{
    #pragma unroll
    for (int kh = 0; kh < 4; ++kh) {     // 4 x k16 within KC=64
        uint32_t ah[4][4];
        uint32_t arow = (uint32_t)(m0w + (lane & 15));
        uint32_t ac   = (uint32_t)(kh * 2 + (lane >> 4));     // 0..7
        #pragma unroll
        for (int mt = 0; mt < 4; ++mt)
            ldmx4(ah[mt], st + swz(arow + mt * 16, ac));
        uint32_t bh[2][4];
        uint32_t brow = (uint32_t)(n0w + (lane & 7) + ((lane >> 4) << 3));
        uint32_t bc   = (uint32_t)(kh * 2 + ((lane & 8) >> 3));
        #pragma unroll
        for (int bj = 0; bj < 2; ++bj)
            ldmx4(bh[bj], st + B_OFF + swz(brow + bj * 16, bc));
        #pragma unroll
        for (int mt = 0; mt < 4; ++mt)
            #pragma unroll
            for (int nt = 0; nt < 4; ++nt)
                mma16816(acc[mt][nt], ah[mt], &bh[nt >> 1][(nt & 1) * 2]);
    }
}

// ---------------------------------------------------------------------------
// GEMM #1: C[16384,2048] = x @ Wkv^T (fp16) + fused ||k||, wv epilogue
// ---------------------------------------------------------------------------
__global__ __launch_bounds__(256, 2) void kv_gemm_kernel(
    const float* __restrict__ kb, const float* __restrict__ vb)
{
    extern __shared__ char sp[];
    __shared__ float s_kb[64], s_vb[64];
    const int t    = threadIdx.x;
    const int lane = t & 31;
    const int w    = t >> 5;
    const int m0w  = (w >> 2) * 64;
    const int n0w  = (w & 3) * 32;
    const int m0   = blockIdx.x * 128;
    const int h    = blockIdx.y;          // head
    const int n0   = h * 128;
    uint32_t sb = smem_u32(sp);

    if (t < 64)       s_kb[t]      = kb[h * 64 + t];
    else if (t < 128) s_vb[t - 64] = vb[h * 64 + t - 64];

    float acc[4][4][4];
    #pragma unroll
    for (int a = 0; a < 4; ++a)
        #pragma unroll
        for (int b = 0; b < 4; ++b)
            #pragma unroll
            for (int q = 0; q < 4; ++q) acc[a][b][q] = 0.f;

    load_stage(g_x, g_wkv, m0, n0, 0, sb,         t); CP_COMMIT();
    load_stage(g_x, g_wkv, m0, n0, 1, sb + STAGE, t); CP_COMMIT();

    for (int s = 0; s < NCH; ++s) {
        if (s + 2 < NCH) { CP_WAIT1(); } else { CP_WAIT0(); }
        __syncthreads();                 // stage s visible; compute(s-1) done
        if (s + 2 < NCH) {
            load_stage(g_x, g_wkv, m0, n0, s + 2, sb + ((s + 2) % 3) * STAGE, t);
            CP_COMMIT();
        }
        compute_stage(sb + (s % 3) * STAGE, m0w, n0w, lane, acc);
    }
    __syncthreads();      // all warps done reading smem before epilogue reuse

    // dump accumulators to smem: 128 x 128 fp32, row pitch 132
    float* sC = reinterpret_cast<float*>(sp);
    #pragma unroll
    for (int mt = 0; mt < 4; ++mt)
        #pragma unroll
        for (int nt = 0; nt < 4; ++nt) {
            int r = m0w + mt * 16 + (lane >> 2);
            int c = n0w + nt * 8 + ((lane & 3) << 1);
            sC[r * 132 + c]           = acc[mt][nt][0];
            sC[r * 132 + c + 1]       = acc[mt][nt][1];
            sC[(r + 8) * 132 + c]     = acc[mt][nt][2];
            sC[(r + 8) * 132 + c + 1] = acc[mt][nt][3];
        }
    __syncthreads();

    if (t < 128) {
        const float* row = sC + t * 132;
        float ssq = 0.f;
        #pragma unroll
        for (int j = 0; j < 64; ++j) {
            float kv = row[j] + s_kb[j];
            ssq = fmaf(kv, kv, ssq);
        }
        float m = sqrtf(ssq);
        float* dst = g_wv + (size_t)(m0 + t) * DD + h * 64;
        #pragma unroll
        for (int j4 = 0; j4 < 16; ++j4) {
            float4 o;
            o.x = (row[64 + j4*4 + 0] + s_vb[j4*4 + 0]) * m;
            o.y = (row[64 + j4*4 + 1] + s_vb[j4*4 + 1]) * m;
            o.z = (row[64 + j4*4 + 2] + s_vb[j4*4 + 2]) * m;
            o.w = (row[64 + j4*4 + 3] + s_vb[j4*4 + 3]) * m;
            *reinterpret_cast<float4*>(dst + j4 * 4) = o;
        }
    }
}

// ---------------------------------------------------------------------------
// GEMM #2: out rows = A @ ow^T + ob, scattered directly to all tokens per bin
// ---------------------------------------------------------------------------
__global__ __launch_bounds__(256, 2) void out_gemm_kernel(
    const float* __restrict__ ob, float* __restrict__ out)
{
    extern __shared__ char sp[];
    __shared__ float s_ob[128];
    const int t    = threadIdx.x;
    const int lane = t & 31;
    const int w    = t >> 5;
    const int m0w  = (w >> 2) * 64;
    const int n0w  = (w & 3) * 32;
    const int m0   = blockIdx.x * 128;    // rows m = b*512 + g
    const int j0   = blockIdx.y * 128;
    uint32_t sb = smem_u32(sp);

    if (t < 128) s_ob[t] = ob[j0 + t];

    float acc[4][4][4];
    #pragma unroll
    for (int a = 0; a < 4; ++a)
        #pragma unroll
        for (int b = 0; b < 4; ++b)
            #pragma unroll
            for (int q = 0; q < 4; ++q) acc[a][b][q] = 0.f;

    load_stage(g_A, g_ow, m0, j0, 0, sb,         t); CP_COMMIT();
    load_stage(g_A, g_ow, m0, j0, 1, sb + STAGE, t); CP_COMMIT();

    for (int s = 0; s < NCH; ++s) {
        if (s + 2 < NCH) { CP_WAIT1(); } else { CP_WAIT0(); }
        __syncthreads();
        if (s + 2 < NCH) {
            load_stage(g_A, g_ow, m0, j0, s + 2, sb + ((s + 2) % 3) * STAGE, t);
            CP_COMMIT();
        }
        compute_stage(sb + (s % 3) * STAGE, m0w, n0w, lane, acc);
    }

    // epilogue: scatter each bin-row to every token n with bin_of(n) == g
    const int b = m0 >> 9;          // batch (512 bins per batch, m0 multiple of 128)
    #pragma unroll
    for (int mt = 0; mt < 4; ++mt) {
        #pragma unroll
        for (int half = 0; half < 2; ++half) {
            int m = m0 + m0w + mt * 16 + (lane >> 2) + half * 8;
            int g = m & 511;
            int n = (int)(((long long)g * 4095) / 511) - 2;
            if (n < 0) n = 0;
            while (bin_of(n) < g) ++n;
            for (; n < NN && bin_of(n) == g; ++n) {
                float* dst = out + (((size_t)(b * NN + n)) << 10) + j0;
                #pragma unroll
                for (int nt = 0; nt < 4; ++nt) {
                    int cl = n0w + nt * 8 + ((lane & 3) << 1);
                    float2 o;
                    o.x = acc[mt][nt][half * 2 + 0] + s_ob[cl];
                    o.y = acc[mt][nt][half * 2 + 1] + s_ob[cl + 1];
                    *reinterpret_cast<float2*>(dst + cl) = o;
                }
            }
        }
    }
}

// ---------------------------------------------------------------------------
// segment-sum into field
// ---------------------------------------------------------------------------
__global__ void field_kernel()
{
    int g  = blockIdx.x;
    int bh = blockIdx.y;
    int b  = bh >> 4, h = bh & 15;
    int d  = threadIdx.x;
    int n0 = (int)(((long long)g * 4095) / 511) - 2;
    if (n0 < 0) n0 = 0;
    float s = 0.f;
    for (int n = n0; n < n0 + 14 && n < NN; ++n) {
        if (bin_of(n) == g)
            s += g_wv[((size_t)(b * NN + n)) * DD + h * HDIM + d];
    }
    g_field[((size_t)bh * GG + g) * HDIM + d] = s;
}

// ---------------------------------------------------------------------------
// circular exp-kernel convolution (anchor + geometric recursion);
// writes the out-GEMM A matrix directly: fp16, layout (b*512+g, h*64+d)
// ---------------------------------------------------------------------------
#define TAPS 144
__global__ void conv_kernel()
{
    extern __shared__ float sf[];
    __shared__ float wsh[TAPS];
    int bh = blockIdx.x;
    int b  = bh >> 4, h = bh & 15;
    const float* F = g_field + (size_t)bh * GG * HDIM;
    for (int i = threadIdx.x; i < GG * HDIM; i += blockDim.x)
        sf[i] = F[i];
    if (threadIdx.x < TAPS) {
        float Z = 0.f;
        for (int dd = 256; dd >= 1; --dd) Z += expf(-(float)dd / 3.0f);
        Z += 1e-8f;
        wsh[threadIdx.x] = expf(-(float)(threadIdx.x + 1) / 3.0f) / Z;
    }
    __syncthreads();

    int d    = threadIdx.x & 63;
    int g0   = (threadIdx.x >> 6) * 64;
    int gtop = g0 + 63;

    float acc = 0.f;
    for (int j = TAPS - 1; j >= 0; --j)
        acc = fmaf(wsh[j], sf[((gtop + 257 + j) & 511) * HDIM + d], acc);

    __half* outA = g_A + ((size_t)b * GG << 10) + h * 64 + d;
    outA[(size_t)gtop << 10] = __float2half(acc);

    const float a  = 0.7165313105737893f;
    const float w0 = wsh[0];
    float C = acc;
    for (int g = gtop - 1; g >= g0; --g) {
        C = fmaf(a, C, w0 * sf[((g + 257) & 511) * HDIM + d]);
        outA[(size_t)g << 10] = __float2half(C);
    }
}

// ---------------------------------------------------------------------------
extern "C" void kernel_launch(void* const* d_in, const int* in_sizes, int n_in,
                              void* d_out, int out_size)
{
    const float* x  = (const float*)d_in[0];
    // d_in[1], d_in[2] are q_w, q_b — unused by the reference output.
    const float* kw = (const float*)d_in[3];
    const float* kb = (const float*)d_in[4];
    const float* vw = (const float*)d_in[5];
    const float* vb = (const float*)d_in[6];
    const float* ow = (const float*)d_in[7];
    const float* ob = (const float*)d_in[8];
    float* out = (float*)d_out;

    cudaFuncSetAttribute(kv_gemm_kernel,  cudaFuncAttributeMaxDynamicSharedMemorySize, DSMEM);
    cudaFuncSetAttribute(out_gemm_kernel, cudaFuncAttributeMaxDynamicSharedMemorySize, DSMEM);
    cudaFuncSetAttribute(conv_kernel, cudaFuncAttributeMaxDynamicSharedMemorySize,
                         GG * HDIM * (int)sizeof(float));

    conv_x_kernel<<<(BNTOK * DD / 4) / 256, 256>>>(x);
    conv_wkv_kernel<<<(2048 * DD / 4) / 256, 256>>>(kw, vw);
    conv_ow_kernel<<<(DD * DD / 4) / 256, 256>>>(ow);

    kv_gemm_kernel<<<dim3(BNTOK / 128, HH), 256, DSMEM>>>(kb, vb);

    field_kernel<<<dim3(GG, BB * HH), 64>>>();
    conv_kernel<<<BB * HH, 512, GG * HDIM * sizeof(float)>>>();

    out_gemm_kernel<<<dim3((BB * GG) / 128, DD / 128), 256, DSMEM>>>(ob, out);
}

// round 9
// speedup vs baseline: 5.5611x; 1.0215x over previous
#include <cuda_runtime.h>
#include <cuda_fp16.h>
#include <math.h>
#include <stdint.h>

#define BB 4
#define NN 4096
#define DD 1024
#define HH 16
#define HDIM 64
#define GG 512
#define BNTOK (BB*NN)

// ---------------- scratch (device globals; no allocations allowed) ----------
__device__ float g_field[(size_t)BB * HH * GG * HDIM];  // 8MB (atomic-accumulated)

// fp16 operands (plain fp16: validated error budget, rel_err ~4e-4 vs 1e-3 gate)
__device__ __half g_x  [(size_t)BNTOK * DD];            // 32MB
__device__ __half g_wkv[(size_t)2048 * DD];             // 4MB  packed [k|v] per head
__device__ __half g_ow [(size_t)DD * DD];               // 2MB
__device__ __half g_A  [(size_t)BB * GG * DD];          // 4MB  conv result, repacked

// Replicates jnp: pos = (n/4095.0f)*511.0f ; int32 trunc ; clip
__device__ __forceinline__ int bin_of(int n) {
    float p = ((float)n / 4095.0f) * 511.0f;
    int g = (int)p;
    g = g < 0 ? 0 : g;
    return g > 511 ? 511 : g;
}

// ---------------- baseline-PTX tensor helpers (sm_80+, ok on compute_103) ---
__device__ __forceinline__ uint32_t smem_u32(const void* p) {
    uint32_t a;
    asm("{ .reg .u64 t; cvta.to.shared.u64 t, %1; cvt.u32.u64 %0, t; }" : "=r"(a) : "l"(p));
    return a;
}
__device__ __forceinline__ void ldmx4(uint32_t* r, uint32_t a) {
    asm volatile("ldmatrix.sync.aligned.m8n8.x4.shared.b16 {%0,%1,%2,%3}, [%4];"
        : "=r"(r[0]), "=r"(r[1]), "=r"(r[2]), "=r"(r[3]) : "r"(a));
}
__device__ __forceinline__ void mma16816(float* c, const uint32_t* a, const uint32_t* b) {
    asm volatile("mma.sync.aligned.m16n8k16.row.col.f32.f16.f16.f32 "
        "{%0,%1,%2,%3}, {%4,%5,%6,%7}, {%8,%9}, {%0,%1,%2,%3};"
        : "+f"(c[0]), "+f"(c[1]), "+f"(c[2]), "+f"(c[3])
        : "r"(a[0]), "r"(a[1]), "r"(a[2]), "r"(a[3]), "r"(b[0]), "r"(b[1]));
}
#define CP_ASYNC(d, s) asm volatile("cp.async.cg.shared.global [%0], [%1], 16;" :: "r"(d), "l"(s) : "memory")
#define CP_COMMIT()    asm volatile("cp.async.commit_group;" ::: "memory")
#define CP_WAIT1()     asm volatile("cp.async.wait_group 1;" ::: "memory")
#define CP_WAIT0()     asm volatile("cp.async.wait_group 0;" ::: "memory")

// Tiling: block 128x128. kv: 4 warps (2x2), warp tile 64x64 (MMA:ldmx = 4:1).
// out: 8 warps (2x4), warp tile 64x32. Stage: A 16KB | B 16KB = 32KB;
// 3 stages = 96KB -> 2 CTAs/SM. 128B rows (64 fp16 = K chunk), Swizzle<3,4,3>.
#define KC       64
#define NCH      16                 // 1024 / 64
#define B_OFF    16384
#define STAGE    32768
#define DSMEM    (3*STAGE)          // 98304

// swizzled byte offset for (row, 16B-chunk c in 0..7)
__device__ __forceinline__ uint32_t swz(uint32_t row, uint32_t c) {
    return row * 128u + ((c ^ (row & 7u)) << 4);
}

// ---------------------------------------------------------------------------
// fp32 -> fp16 conversions + field zero
// ---------------------------------------------------------------------------
__global__ void conv_x_kernel(const float* __restrict__ x)
{
    size_t i = (size_t)blockIdx.x * blockDim.x + threadIdx.x;
    float4 v = reinterpret_cast<const float4*>(x)[i];
    __half2* X = reinterpret_cast<__half2*>(g_x);
    X[2*i]   = __half2(__float2half(v.x), __float2half(v.y));
    X[2*i+1] = __half2(__float2half(v.z), __float2half(v.w));
}

__global__ void conv_wkv_kernel(const float* __restrict__ kw, const float* __restrict__ vw)
{
    size_t i = (size_t)blockIdx.x * blockDim.x + threadIdx.x;   // over 2048*1024/4
    size_t e = i * 4;
    int r = (int)(e >> 10), c = (int)(e & 1023);
    int h = r >> 7, r7 = r & 127;
    const float* src = (r7 < 64) ? (kw + ((size_t)(h*64 + r7)) * DD + c)
                                 : (vw + ((size_t)(h*64 + r7 - 64)) * DD + c);
    float4 v = *reinterpret_cast<const float4*>(src);
    __half2* W = reinterpret_cast<__half2*>(g_wkv);
    W[2*i]   = __half2(__float2half(v.x), __float2half(v.y));
    W[2*i+1] = __half2(__float2half(v.z), __float2half(v.w));
}

__global__ void conv_ow_kernel(const float* __restrict__ ow)
{
    size_t i = (size_t)blockIdx.x * blockDim.x + threadIdx.x;
    float4 v = reinterpret_cast<const float4*>(ow)[i];
    __half2* W = reinterpret_cast<__half2*>(g_ow);
    W[2*i]   = __half2(__float2half(v.x), __float2half(v.y));
    W[2*i+1] = __half2(__float2half(v.z), __float2half(v.w));
}

__global__ void zero_field_kernel()
{
    size_t i = (size_t)blockIdx.x * blockDim.x + threadIdx.x;   // over 2M/4
    reinterpret_cast<float4*>(g_field)[i] = make_float4(0.f, 0.f, 0.f, 0.f);
}

// ---------------------------------------------------------------------------
// shared load (templated on thread count)
// ---------------------------------------------------------------------------
template <int NTHR>
__device__ __forceinline__ void load_stage(
    const __half* __restrict__ gA, const __half* __restrict__ gB,
    int m0, int n0, int kc, uint32_t sbase, int t)
{
    #pragma unroll
    for (int i = 0; i < 1024 / NTHR; ++i) {    // A: 128 rows x 8 chunks of 16B
        int e = t + i * NTHR;
        int row = e >> 3, c = e & 7;
        CP_ASYNC(sbase + swz(row, c),
                 gA + (((size_t)(m0 + row)) << 10) + (size_t)kc * KC + c * 8);
    }
    #pragma unroll
    for (int i = 0; i < 1024 / NTHR; ++i) {    // B
        int e = t + i * NTHR;
        int row = e >> 3, c = e & 7;
        CP_ASYNC(sbase + B_OFF + swz(row, c),
                 gB + (((size_t)(n0 + row)) << 10) + (size_t)kc * KC + c * 8);
    }
}

// ---------------------------------------------------------------------------
// GEMM #1: C[16384,2048] = x @ Wkv^T (fp16), 4 warps, warp tile 64x64.
// Fused epilogue: ||k||, wv = (v+vb)*||k||, per-block bin reduction,
// atomicAdd partial sums into g_field. No g_wv round-trip.
// ---------------------------------------------------------------------------
__global__ __launch_bounds__(128, 2) void kv_gemm_kernel(
    const float* __restrict__ kb, const float* __restrict__ vb)
{
    extern __shared__ char sp[];
    __shared__ float s_kb[64], s_vb[64];
    const int t    = threadIdx.x;
    const int lane = t & 31;
    const int w    = t >> 5;            // 0..3
    const int m0w  = (w >> 1) * 64;
    const int n0w  = (w & 1) * 64;
    const int m0   = blockIdx.x * 128;  // global token base
    const int h    = blockIdx.y;        // head
    const int n0   = h * 128;
    uint32_t sb = smem_u32(sp);

    if (t < 64)       s_kb[t]      = kb[h * 64 + t];
    else if (t < 128) s_vb[t - 64] = vb[h * 64 + t - 64];

    float acc[4][8][4];
    #pragma unroll
    for (int a = 0; a < 4; ++a)
        #pragma unroll
        for (int b = 0; b < 8; ++b)
            #pragma unroll
            for (int q = 0; q < 4; ++q) acc[a][b][q] = 0.f;

    load_stage<128>(g_x, g_wkv, m0, n0, 0, sb,         t); CP_COMMIT();
    load_stage<128>(g_x, g_wkv, m0, n0, 1, sb + STAGE, t); CP_COMMIT();

    for (int s = 0; s < NCH; ++s) {
        if (s + 2 < NCH) { CP_WAIT1(); } else { CP_WAIT0(); }
        __syncthreads();
        if (s + 2 < NCH) {
            load_stage<128>(g_x, g_wkv, m0, n0, s + 2, sb + ((s + 2) % 3) * STAGE, t);
            CP_COMMIT();
        }
        uint32_t st = sb + (s % 3) * STAGE;
        #pragma unroll
        for (int kh = 0; kh < 4; ++kh) {
            uint32_t ah[4][4];
            uint32_t arow = (uint32_t)(m0w + (lane & 15));
            uint32_t ac   = (uint32_t)(kh * 2 + (lane >> 4));
            #pragma unroll
            for (int mt = 0; mt < 4; ++mt)
                ldmx4(ah[mt], st + swz(arow + mt * 16, ac));
            uint32_t bh[4][4];
            uint32_t brow = (uint32_t)(n0w + (lane & 7) + ((lane >> 4) << 3));
            uint32_t bc   = (uint32_t)(kh * 2 + ((lane & 8) >> 3));
            #pragma unroll
            for (int bj = 0; bj < 4; ++bj)
                ldmx4(bh[bj], st + B_OFF + swz(brow + bj * 16, bc));
            #pragma unroll
            for (int mt = 0; mt < 4; ++mt)
                #pragma unroll
                for (int nt = 0; nt < 8; ++nt)
                    mma16816(acc[mt][nt], ah[mt], &bh[nt >> 1][(nt & 1) * 2]);
        }
    }
    __syncthreads();      // all warps done reading smem before epilogue reuse

    // dump accumulators: 128 x 128 fp32, pitch 132
    float* sC = reinterpret_cast<float*>(sp);
    #pragma unroll
    for (int mt = 0; mt < 4; ++mt)
        #pragma unroll
        for (int nt = 0; nt < 8; ++nt) {
            int r = m0w + mt * 16 + (lane >> 2);
            int c = n0w + nt * 8 + ((lane & 3) << 1);
            sC[r * 132 + c]           = acc[mt][nt][0];
            sC[r * 132 + c + 1]       = acc[mt][nt][1];
            sC[(r + 8) * 132 + c]     = acc[mt][nt][2];
            sC[(r + 8) * 132 + c + 1] = acc[mt][nt][3];
        }
    __syncthreads();

    // per-token: ||k|| then overwrite cols [0,64) of own row with wv values
    {
        float* row = sC + t * 132;
        float ssq = 0.f;
        #pragma unroll
        for (int j = 0; j < 64; ++j) {
            float kv = row[j] + s_kb[j];
            ssq = fmaf(kv, kv, ssq);
        }
        float m = sqrtf(ssq);
        #pragma unroll
        for (int j = 0; j < 64; ++j)
            row[j] = (row[64 + j] + s_vb[j]) * m;
    }
    __syncthreads();

    // bin reduction: sum wv rows per bin, one atomicAdd per (bin, d)
    {
        const int b      = m0 >> 12;            // batch (4096 tokens each)
        const int nloc0  = m0 & (NN - 1);       // block-local token base within batch
        const int g_lo   = bin_of(nloc0);
        const int g_hi   = bin_of(nloc0 + 127);
        const int nb     = g_hi - g_lo + 1;     // <= 18
        float* fdst = g_field + (((size_t)(b * HH + h)) * GG << 6);
        for (int idx = t; idx < nb * 64; idx += 128) {
            int bin = g_lo + (idx >> 6);
            int d   = idx & 63;
            int n   = (int)(((long long)bin * 4095) / 511) - 2;
            if (n < 0) n = 0;
            while (bin_of(n) < bin) ++n;
            if (n < nloc0) n = nloc0;
            float s = 0.f;
            for (; n < nloc0 + 128 && n < NN && bin_of(n) == bin; ++n)
                s += sC[(n - nloc0) * 132 + d];
            atomicAdd(fdst + ((size_t)bin << 6) + d, s);
        }
    }
}

// ---------------------------------------------------------------------------
// GEMM #2: out rows = A @ ow^T + ob, scattered directly to all tokens per bin
// (8 warps, warp tile 64x32 — kernel is small, keep proven config)
// ---------------------------------------------------------------------------
__global__ __launch_bounds__(256, 2) void out_gemm_kernel(
    const float* __restrict__ ob, float* __restrict__ out)
{
    extern __shared__ char sp[];
    __shared__ float s_ob[128];
    const int t    = threadIdx.x;
    const int lane = t & 31;
    const int w    = t >> 5;
    const int m0w  = (w >> 2) * 64;
    const int n0w  = (w & 3) * 32;
    const int m0   = blockIdx.x * 128;    // rows m = b*512 + g
    const int j0   = blockIdx.y * 128;
    uint32_t sb = smem_u32(sp);

    if (t < 128) s_ob[t] = ob[j0 + t];

    float acc[4][4][4];
    #pragma unroll
    for (int a = 0; a < 4; ++a)
        #pragma unroll
        for (int b = 0; b < 4; ++b)
            #pragma unroll
            for (int q = 0; q < 4; ++q) acc[a][b][q] = 0.f;

    load_stage<256>(g_A, g_ow, m0, j0, 0, sb,         t); CP_COMMIT();
    load_stage<256>(g_A, g_ow, m0, j0, 1, sb + STAGE, t); CP_COMMIT();

    for (int s = 0; s < NCH; ++s) {
        if (s + 2 < NCH) { CP_WAIT1(); } else { CP_WAIT0(); }
        __syncthreads();
        if (s + 2 < NCH) {
            load_stage<256>(g_A, g_ow, m0, j0, s + 2, sb + ((s + 2) % 3) * STAGE, t);
            CP_COMMIT();
        }
        uint32_t st = sb + (s % 3) * STAGE;
        #pragma unroll
        for (int kh = 0; kh < 4; ++kh) {
            uint32_t ah[4][4];
            uint32_t arow = (uint32_t)(m0w + (lane & 15));
            uint32_t ac   = (uint32_t)(kh * 2 + (lane >> 4));
            #pragma unroll
            for (int mt = 0; mt < 4; ++mt)
                ldmx4(ah[mt], st + swz(arow + mt * 16, ac));
            uint32_t bh[2][4];
            uint32_t brow = (uint32_t)(n0w + (lane & 7) + ((lane >> 4) << 3));
            uint32_t bc   = (uint32_t)(kh * 2 + ((lane & 8) >> 3));
            #pragma unroll
            for (int bj = 0; bj < 2; ++bj)
                ldmx4(bh[bj], st + B_OFF + swz(brow + bj * 16, bc));
            #pragma unroll
            for (int mt = 0; mt < 4; ++mt)
                #pragma unroll
                for (int nt = 0; nt < 4; ++nt)
                    mma16816(acc[mt][nt], ah[mt], &bh[nt >> 1][(nt & 1) * 2]);
        }
    }

    // epilogue: scatter each bin-row to every token n with bin_of(n) == g
    const int b = m0 >> 9;          // batch (512 bins per batch)
    #pragma unroll
    for (int mt = 0; mt < 4; ++mt) {
        #pragma unroll
        for (int half = 0; half < 2; ++half) {
            int m = m0 + m0w + mt * 16 + (lane >> 2) + half * 8;
            int g = m & 511;
            int n = (int)(((long long)g * 4095) / 511) - 2;
            if (n < 0) n = 0;
            while (bin_of(n) < g) ++n;
            for (; n < NN && bin_of(n) == g; ++n) {
                float* dst = out + (((size_t)(b * NN + n)) << 10) + j0;
                #pragma unroll
                for (int nt = 0; nt < 4; ++nt) {
                    int cl = n0w + nt * 8 + ((lane & 3) << 1);
                    float2 o;
                    o.x = acc[mt][nt][half * 2 + 0] + s_ob[cl];
                    o.y = acc[mt][nt][half * 2 + 1] + s_ob[cl + 1];
                    *reinterpret_cast<float2*>(dst + cl) = o;
                }
            }
        }
    }
}

// ---------------------------------------------------------------------------
// circular exp-kernel convolution (anchor + geometric recursion);
// writes the out-GEMM A matrix directly: fp16, layout (b*512+g, h*64+d)
// ---------------------------------------------------------------------------
#define TAPS 144
__global__ void conv_kernel()
{
    extern __shared__ float sf[];
    __shared__ float wsh[TAPS];
    int bh = blockIdx.x;
    int b  = bh >> 4, h = bh & 15;
    const float* F = g_field + (size_t)bh * GG * HDIM;
    for (int i = threadIdx.x; i < GG * HDIM; i += blockDim.x)
        sf[i] = F[i];
    if (threadIdx.x < TAPS) {
        float Z = 0.f;
        for (int dd = 256; dd >= 1; --dd) Z += expf(-(float)dd / 3.0f);
        Z += 1e-8f;
        wsh[threadIdx.x] = expf(-(float)(threadIdx.x + 1) / 3.0f) / Z;
    }
    __syncthreads();

    int d    = threadIdx.x & 63;
    int g0   = (threadIdx.x >> 6) * 64;
    int gtop = g0 + 63;

    float acc = 0.f;
    for (int j = TAPS - 1; j >= 0; --j)
        acc = fmaf(wsh[j], sf[((gtop + 257 + j) & 511) * HDIM + d], acc);

    __half* outA = g_A + ((size_t)b * GG << 10) + h * 64 + d;
    outA[(size_t)gtop << 10] = __float2half(acc);

    const float a  = 0.7165313105737893f;
    const float w0 = wsh[0];
    float C = acc;
    for (int g = gtop - 1; g >= g0; --g) {
        C = fmaf(a, C, w0 * sf[((g + 257) & 511) * HDIM + d]);
        outA[(size_t)g << 10] = __float2half(C);
    }
}

// ---------------------------------------------------------------------------
extern "C" void kernel_launch(void* const* d_in, const int* in_sizes, int n_in,
                              void* d_out, int out_size)
{
    const float* x  = (const float*)d_in[0];
    // d_in[1], d_in[2] are q_w, q_b — unused by the reference output.
    const float* kw = (const float*)d_in[3];
    const float* kb = (const float*)d_in[4];
    const float* vw = (const float*)d_in[5];
    const float* vb = (const float*)d_in[6];
    const float* ow = (const float*)d_in[7];
    const float* ob = (const float*)d_in[8];
    float* out = (float*)d_out;

    cudaFuncSetAttribute(kv_gemm_kernel,  cudaFuncAttributeMaxDynamicSharedMemorySize, DSMEM);
    cudaFuncSetAttribute(out_gemm_kernel, cudaFuncAttributeMaxDynamicSharedMemorySize, DSMEM);
    cudaFuncSetAttribute(conv_kernel, cudaFuncAttributeMaxDynamicSharedMemorySize,
                         GG * HDIM * (int)sizeof(float));

    conv_x_kernel<<<(BNTOK * DD / 4) / 256, 256>>>(x);
    conv_wkv_kernel<<<(2048 * DD / 4) / 256, 256>>>(kw, vw);
    conv_ow_kernel<<<(DD * DD / 4) / 256, 256>>>(ow);
    zero_field_kernel<<<(BB * HH * GG * HDIM / 4) / 256, 256>>>();

    kv_gemm_kernel<<<dim3(BNTOK / 128, HH), 128, DSMEM>>>(kb, vb);

    conv_kernel<<<BB * HH, 512, GG * HDIM * sizeof(float)>>>();

    out_gemm_kernel<<<dim3((BB * GG) / 128, DD / 128), 256, DSMEM>>>(ob, out);
}